// round 7
// baseline (speedup 1.0000x reference)
#include <cuda_runtime.h>
#include <math.h>
#include <math_constants.h>

#define D_MODEL 768
#define N_BR    4
#define DH      64
#define H_TOT   48
#define BATCH   2
#define T_LEN   1024
#define M_ROWS  2048
#define NQ      3072

typedef unsigned long long u64;
typedef unsigned int u32;

// ---- packed fp32x2 helpers ----
__device__ __forceinline__ u64 f2fma(u64 a, u64 b, u64 c) {
    u64 d; asm("fma.rn.f32x2 %0, %1, %2, %3;" : "=l"(d) : "l"(a), "l"(b), "l"(c)); return d;
}
__device__ __forceinline__ u64 f2pack(float lo, float hi) {
    u64 d; asm("mov.b64 %0, {%1, %2};" : "=l"(d) : "f"(lo), "f"(hi)); return d;
}
__device__ __forceinline__ float2 f2unpack(u64 a) {
    float lo, hi; asm("mov.b64 {%0, %1}, %2;" : "=f"(lo), "=f"(hi) : "l"(a)); return make_float2(lo, hi);
}
__device__ __forceinline__ float f2sum(u64 a) { float2 v = f2unpack(a); return v.x + v.y; }

// ---- tf32 split ----
__device__ __forceinline__ float2 tf32split(float x) {
    u32 hb; asm("cvt.rna.tf32.f32 %0, %1;" : "=r"(hb) : "f"(x));
    float hf = __uint_as_float(hb);
    float lo = x - hf;
    u32 lb; asm("cvt.rna.tf32.f32 %0, %1;" : "=r"(lb) : "f"(lo));
    return make_float2(hf, __uint_as_float(lb));
}

#define MMA_TF32(ACC, A0, A1, A2, A3, B0, B1)                                        \
    asm volatile("mma.sync.aligned.m16n8k8.row.col.f32.tf32.tf32.f32 "               \
                 "{%0,%1,%2,%3}, {%4,%5,%6,%7}, {%8,%9}, {%0,%1,%2,%3};"             \
                 : "+f"(ACC[0]), "+f"(ACC[1]), "+f"(ACC[2]), "+f"(ACC[3])            \
                 : "r"(A0), "r"(A1), "r"(A2), "r"(A3), "r"(B0), "r"(B1))

// ---- scratch ----
__device__ float  g_wq2f[NQ * D_MODEL];        // folded WQ (float)
__device__ float  g_wk2f[NQ * D_MODEL];        // folded WK, 48 head-variants (float)
__device__ float  g_bk2 [NQ];                  // folded K bias
__device__ float  g_wotf[D_MODEL * NQ];        // WO as [n][br*768+c]
__device__ float2 g_q2  [(size_t)M_ROWS * NQ]; // q roped, split (hi,lo), [bh][t][d]
__device__ float2 g_k2  [(size_t)M_ROWS * NQ]; // k roped, split
__device__ float  g_ctx [(size_t)M_ROWS * NQ]; // [b*1024+t][br*768+c]
__device__ float2 g_ropetab[T_LEN * 32];
__device__ int4   g_topi [BATCH * H_TOT * T_LEN];
__device__ float4 g_topw [BATCH * H_TOT * T_LEN];
__device__ float  g_psink[BATCH * H_TOT * T_LEN];

// ================= prep_w: fold wedge into WQ/WK (+bias), relayout WO ============
__global__ __launch_bounds__(256) void prep_w(const float* __restrict__ WQw,
                                              const float* __restrict__ WKw,
                                              const float* __restrict__ WKb,
                                              const float* __restrict__ wedgeA,
                                              const float* __restrict__ wbias,
                                              const float* __restrict__ WOw) {
    __shared__ float sk[4096];
    __shared__ float Ws[64 * 68];
    __shared__ float tile[32][33];
    const int blk = blockIdx.x, tid = threadIdx.x;

    if (blk < 1152) {
        const bool isK = blk >= 576;
        const int b2 = isK ? blk - 576 : blk;
        const int h = b2 / 12, c0 = (b2 % 12) * 64;
        const int hs = isK ? (h % 12) : h;
        const float* Wsrc = isK ? WKw : WQw;
        for (int i = tid; i < 4096; i += 256) {
            int e = i >> 6, d = i & 63;
            sk[i] = wedgeA[e * 64 + d] - wedgeA[d * 64 + e];
        }
        for (int i = tid; i < 4096; i += 256) {
            int e = i >> 6, c = i & 63;
            Ws[e * 68 + c] = Wsrc[(size_t)(hs * 64 + e) * D_MODEL + c0 + c];
        }
        __syncthreads();
        const int d = tid >> 2, cg = (tid & 3) * 16;
        float outv[16];
        const float bd = 1.0f + wbias[h * 64 + d];
#pragma unroll
        for (int u = 0; u < 16; u++) outv[u] = bd * Ws[d * 68 + cg + u];
        for (int e = 0; e < 64; ++e) {
            float s = sk[e * 64 + d];
            const float* wr = &Ws[e * 68 + cg];
#pragma unroll
            for (int u = 0; u < 16; u++) outv[u] = fmaf(s, wr[u], outv[u]);
        }
        float* dst = (isK ? g_wk2f : g_wq2f) + (size_t)(h * 64 + d) * D_MODEL + c0 + cg;
#pragma unroll
        for (int u = 0; u < 16; u++) dst[u] = outv[u];

        if (isK && c0 == 0 && tid < 64) {
            float acc = (1.0f + wbias[h * 64 + tid]) * WKb[hs * 64 + tid];
            for (int s = 0; s < 64; ++s) acc += sk[s * 64 + tid] * WKb[hs * 64 + s];
            g_bk2[h * 64 + tid] = acc;
        }
    } else {
        const int b3 = blk - 1152;
        const int br = b3 / 576, rem = b3 % 576;
        const int cb = (rem / 24) * 32, nb = (rem % 24) * 32;
        const int tx = tid & 31, ty = tid >> 5;
        for (int r = ty; r < 32; r += 8)
            tile[r][tx] = WOw[((size_t)br * D_MODEL + cb + r) * D_MODEL + nb + tx];
        __syncthreads();
        for (int r = ty; r < 32; r += 8)
            g_wotf[(size_t)(nb + r) * NQ + br * D_MODEL + cb + tx] = tile[tx][r];
    }
}

// ================= rope table =================
__global__ void ropetab_kernel() {
    int idx = blockIdx.x * 256 + threadIdx.x;
    int t = idx >> 5, i = idx & 31;
    float inv = exp2f(-(float)i * 0.41524101186092034f);
    float fr = (float)t * inv;
    g_ropetab[idx] = make_float2(cosf(fr), sinf(fr));
}

// ================= R4-style tf32-3x NT GEMM (in-loop split staging) ==============
// MODE 0: QK projections. z=0: A0 @ wq2f -> rope -> g_q2 (split)
//                         z=1: A1 @ wk2f + bk2 -> rope -> g_k2 (split)
// MODE 2: g_ctx @ wotf, Y = 0.25*acc + 0.25*sum_br aux
template <int MODE>
__global__ __launch_bounds__(256) void gemm_tf32_kernel(const float* __restrict__ A0,
                                                        const float* __restrict__ A1,
                                                        int K,
                                                        const float* __restrict__ aux,
                                                        float* __restrict__ outp) {
    __shared__ float2 As2[16 * 132];
    __shared__ float2 Bs2[16 * 68];

    const int tid = threadIdx.x;
    const int m0 = blockIdx.y * 128, n0 = blockIdx.x * 64;
    const int warpId = tid >> 5, lane = tid & 31;
    const int warpM = warpId & 3, warpN = warpId >> 2;
    const int g = lane >> 2, tg = lane & 3;
    const int sa_m = tid >> 1, sa_k = (tid & 1) * 8;
    const int sb_n = tid & 63, sb_k = (tid >> 6) * 4;

    const float* Aop;
    const float* Bop;
    if (MODE == 0) {
        Aop = blockIdx.z ? A1 : A0;
        Bop = blockIdx.z ? g_wk2f : g_wq2f;
    } else {
        Aop = g_ctx;
        Bop = g_wotf;
    }

    float acc[2][4][4];
#pragma unroll
    for (int mf = 0; mf < 2; mf++)
#pragma unroll
        for (int nf = 0; nf < 4; nf++)
#pragma unroll
            for (int r = 0; r < 4; r++) acc[mf][nf][r] = 0.f;

    const float* Arow = Aop + (size_t)(m0 + sa_m) * K + sa_k;
    const float* Brow = Bop + (size_t)(n0 + sb_n) * K + sb_k;

    float4 pa0 = *(const float4*)(Arow);
    float4 pa1 = *(const float4*)(Arow + 4);
    float4 pb  = *(const float4*)(Brow);

    for (int k0 = 0; k0 < K; k0 += 16) {
        __syncthreads();
        {
            float av[8] = {pa0.x, pa0.y, pa0.z, pa0.w, pa1.x, pa1.y, pa1.z, pa1.w};
#pragma unroll
            for (int j = 0; j < 8; j++) As2[(sa_k + j) * 132 + sa_m] = tf32split(av[j]);
            float bv[4] = {pb.x, pb.y, pb.z, pb.w};
#pragma unroll
            for (int j = 0; j < 4; j++) Bs2[(sb_k + j) * 68 + sb_n] = tf32split(bv[j]);
        }
        __syncthreads();
        if (k0 + 16 < K) {
            pa0 = *(const float4*)(Arow + k0 + 16);
            pa1 = *(const float4*)(Arow + k0 + 20);
            pb  = *(const float4*)(Brow + k0 + 16);
        }
#pragma unroll
        for (int ks = 0; ks < 16; ks += 8) {
            float2 fa[2][4];
#pragma unroll
            for (int mf = 0; mf < 2; mf++) {
                const int rI = warpM * 32 + mf * 16 + g;
                const float2* c0p = &As2[(ks + tg) * 132];
                const float2* c4p = &As2[(ks + tg + 4) * 132];
                fa[mf][0] = c0p[rI];
                fa[mf][1] = c0p[rI + 8];
                fa[mf][2] = c4p[rI];
                fa[mf][3] = c4p[rI + 8];
            }
            float2 fb[4][2];
#pragma unroll
            for (int nf = 0; nf < 4; nf++) {
                const int cI = warpN * 32 + nf * 8 + g;
                fb[nf][0] = Bs2[(ks + tg) * 68 + cI];
                fb[nf][1] = Bs2[(ks + tg + 4) * 68 + cI];
            }
#pragma unroll
            for (int mf = 0; mf < 2; mf++) {
                const u32 ah0 = __float_as_uint(fa[mf][0].x), al0 = __float_as_uint(fa[mf][0].y);
                const u32 ah1 = __float_as_uint(fa[mf][1].x), al1 = __float_as_uint(fa[mf][1].y);
                const u32 ah2 = __float_as_uint(fa[mf][2].x), al2 = __float_as_uint(fa[mf][2].y);
                const u32 ah3 = __float_as_uint(fa[mf][3].x), al3 = __float_as_uint(fa[mf][3].y);
#pragma unroll
                for (int nf = 0; nf < 4; nf++) {
                    const u32 bh0 = __float_as_uint(fb[nf][0].x), bl0 = __float_as_uint(fb[nf][0].y);
                    const u32 bh1 = __float_as_uint(fb[nf][1].x), bl1 = __float_as_uint(fb[nf][1].y);
                    MMA_TF32(acc[mf][nf], al0, al1, al2, al3, bh0, bh1);
                    MMA_TF32(acc[mf][nf], ah0, ah1, ah2, ah3, bl0, bl1);
                    MMA_TF32(acc[mf][nf], ah0, ah1, ah2, ah3, bh0, bh1);
                }
            }
        }
    }

    // ---- epilogue ----
#pragma unroll
    for (int mf = 0; mf < 2; mf++) {
#pragma unroll
        for (int nf = 0; nf < 4; nf++) {
            const int r0 = m0 + warpM * 32 + mf * 16 + g;
            const int r1 = r0 + 8;
            float c0 = acc[mf][nf][0], c1 = acc[mf][nf][1];
            float c2 = acc[mf][nf][2], c3 = acc[mf][nf][3];
            if (MODE == 0) {
                const int h = blockIdx.x;
                const int i = warpN * 16 + nf * 4 + tg;     // rope pair index
                float2* dstbase = blockIdx.z ? g_k2 : g_q2;
                if (blockIdx.z) {
                    const float b0 = g_bk2[h * 64 + 2 * i];
                    const float b1 = g_bk2[h * 64 + 2 * i + 1];
                    c0 += b0; c1 += b1; c2 += b0; c3 += b1;
                }
                {
                    const int t = r0 & 1023, bb = r0 >> 10;
                    float2 rc = g_ropetab[t * 32 + i];
                    float2* qp = &dstbase[(((size_t)(bb * H_TOT + h)) * T_LEN + t) * DH];
                    qp[i]      = tf32split(c0 * rc.x - c1 * rc.y);
                    qp[i + 32] = tf32split(c0 * rc.y + c1 * rc.x);
                }
                {
                    const int t = r1 & 1023, bb = r1 >> 10;
                    float2 rc = g_ropetab[t * 32 + i];
                    float2* qp = &dstbase[(((size_t)(bb * H_TOT + h)) * T_LEN + t) * DH];
                    qp[i]      = tf32split(c2 * rc.x - c3 * rc.y);
                    qp[i + 32] = tf32split(c2 * rc.y + c3 * rc.x);
                }
            } else {
                const int nc = n0 + warpN * 32 + nf * 8 + 2 * tg;
                const float b0 = 0.25f * (aux[nc] + aux[768 + nc] + aux[1536 + nc] + aux[2304 + nc]);
                const float b1 = 0.25f * (aux[nc + 1] + aux[768 + nc + 1] + aux[1536 + nc + 1] + aux[2304 + nc + 1]);
                *(float2*)&outp[(size_t)r0 * 768 + nc] = make_float2(0.25f * c0 + b0, 0.25f * c1 + b1);
                *(float2*)&outp[(size_t)r1 * 768 + nc] = make_float2(0.25f * c2 + b0, 0.25f * c3 + b1);
            }
        }
    }
}

// ================= attn1: tensor-core scores + smem softmax/top-4 ================
// CTA: 128 t-rows of one bh; 256 thr (8 warps, warp w -> rows w*16..w*16+15).
// s-tiles of 64. smem: S[128][65] f32 + K[64][66] float2.
__global__ __launch_bounds__(256, 1) void attn1_kernel(const float* __restrict__ sink) {
    extern __shared__ float smA[];
    float*  Ssm = smA;                        // 128*65 floats
    float2* Ksm = (float2*)(smA + 128 * 65);  // 64*66 float2
    const int bh = blockIdx.y, h = bh % H_TOT;
    const int xt = (gridDim.x - 1) - blockIdx.x;   // heavy tiles first
    const int t0 = xt * 128;
    const int tid = threadIdx.x, warpId = tid >> 5, lane = tid & 31;
    const int g = lane >> 2, tg = lane & 3;

    // Q fragments for this warp's 16 rows (hi,lo)
    float2 qa[8][4];
    {
        const float2* qbase = g_q2 + ((size_t)bh * T_LEN) * DH;
        const int rq = t0 + warpId * 16 + g;
#pragma unroll
        for (int ks = 0; ks < 8; ks++) {
            const int k = ks * 8;
            qa[ks][0] = qbase[(size_t)rq * DH + k + tg];
            qa[ks][1] = qbase[(size_t)(rq + 8) * DH + k + tg];
            qa[ks][2] = qbase[(size_t)rq * DH + k + tg + 4];
            qa[ks][3] = qbase[(size_t)(rq + 8) * DH + k + tg + 4];
        }
    }

    const int t = t0 + tid;   // scan row (tid < 128 only)
    float mrun = -CUDART_INF_F, lrun = 0.f;
    float ts0 = -CUDART_INF_F, ts1 = -CUDART_INF_F, ts2 = -CUDART_INF_F, ts3 = -CUDART_INF_F;
    int ti0 = 0, ti1 = 0, ti2 = 0, ti3 = 0;

    for (int st0 = 0; st0 <= t0 + 127; st0 += 64) {
        // load K tile (64 rows x 64 d), split form
        {
            const float2* kg = g_k2 + ((size_t)bh * T_LEN + st0) * DH;
            for (int i = tid; i < 4096; i += 256) {
                int r = i >> 6, c = i & 63;
                Ksm[r * 66 + c] = kg[r * 64 + c];
            }
        }
        __syncthreads();

        // mma: S[128][64] = Q . K^T   (3-term tf32)
        float sacc[8][4];
#pragma unroll
        for (int nch = 0; nch < 8; nch++)
#pragma unroll
            for (int r = 0; r < 4; r++) sacc[nch][r] = 0.f;

#pragma unroll
        for (int ks = 0; ks < 8; ks++) {
            const u32 ah0 = __float_as_uint(qa[ks][0].x), al0 = __float_as_uint(qa[ks][0].y);
            const u32 ah1 = __float_as_uint(qa[ks][1].x), al1 = __float_as_uint(qa[ks][1].y);
            const u32 ah2 = __float_as_uint(qa[ks][2].x), al2 = __float_as_uint(qa[ks][2].y);
            const u32 ah3 = __float_as_uint(qa[ks][3].x), al3 = __float_as_uint(qa[ks][3].y);
            const int kk = ks * 8;
#pragma unroll
            for (int nch = 0; nch < 8; nch++) {
                const float2 b0 = Ksm[(nch * 8 + g) * 66 + kk + tg];
                const float2 b1 = Ksm[(nch * 8 + g) * 66 + kk + tg + 4];
                const u32 bh0 = __float_as_uint(b0.x), bl0 = __float_as_uint(b0.y);
                const u32 bh1 = __float_as_uint(b1.x), bl1 = __float_as_uint(b1.y);
                MMA_TF32(sacc[nch], al0, al1, al2, al3, bh0, bh1);
                MMA_TF32(sacc[nch], ah0, ah1, ah2, ah3, bl0, bl1);
                MMA_TF32(sacc[nch], ah0, ah1, ah2, ah3, bh0, bh1);
            }
        }

        // dump S to smem
        {
            const int row = warpId * 16 + g;
#pragma unroll
            for (int nch = 0; nch < 8; nch++) {
                const int col = nch * 8 + 2 * tg;
                Ssm[row * 65 + col]           = sacc[nch][0];
                Ssm[row * 65 + col + 1]       = sacc[nch][1];
                Ssm[(row + 8) * 65 + col]     = sacc[nch][2];
                Ssm[(row + 8) * 65 + col + 1] = sacc[nch][3];
            }
        }
        __syncthreads();

        // scalar scan: softmax + top-4 on own row
        if (tid < 128 && t >= st0) {
            const int jmax = min(63, t - st0);
            const float* srow = &Ssm[tid * 65];
            for (int j = 0; j <= jmax; ++j) {
                const float sc = srow[j] * 0.125f;
                if (sc <= mrun) {
                    lrun += __expf(sc - mrun);
                } else {
                    lrun = fmaf(lrun, __expf(mrun - sc), 1.0f);
                    mrun = sc;
                }
                if (sc > ts3) {
                    const int s = st0 + j;
                    if (sc > ts2) {
                        ts3 = ts2; ti3 = ti2;
                        if (sc > ts1) {
                            ts2 = ts1; ti2 = ti1;
                            if (sc > ts0) {
                                ts1 = ts0; ti1 = ti0;
                                ts0 = sc; ti0 = s;
                            } else { ts1 = sc; ti1 = s; }
                        } else { ts2 = sc; ti2 = s; }
                    } else { ts3 = sc; ti3 = s; }
                }
            }
        }
        __syncthreads();
    }

    if (tid < 128) {
        const float sk = sink[h];
        const float mf = fmaxf(mrun, sk);
        const float Z = lrun * __expf(mrun - mf) + __expf(sk - mf);
        const float invZ = 1.0f / Z;
        const float psink = __expf(sk - mf) * invZ;
        float p0 = __expf(ts0 - mf) * invZ;
        float p1 = __expf(ts1 - mf) * invZ;
        float p2 = __expf(ts2 - mf) * invZ;
        float p3 = __expf(ts3 - mf) * invZ;
        const float winv = 1.0f / (p0 + p1 + p2 + p3 + 1e-9f);
        const int o = bh * T_LEN + t;
        g_topi[o]  = make_int4(ti0, ti1, ti2, ti3);
        g_topw[o]  = make_float4(p0 * winv, p1 * winv, p2 * winv, p3 * winv);
        g_psink[o] = psink;
    }
}

// ================= attn2: marker gather + MLP + ctx write ========================
__global__ __launch_bounds__(512) void attn2_kernel(const float* __restrict__ vnull,
                                                    const float* __restrict__ V1w,
                                                    const float* __restrict__ V1b,
                                                    const float* __restrict__ V2w,
                                                    const float* __restrict__ V2b) {
    extern __shared__ float sm2[];
    float* V1s = sm2;                 // 16384
    float* V2t = sm2 + 16384;         // 256*66
    __shared__ float sV1b[256];
    __shared__ float sV2b[64];

    const int bh = blockIdx.y, b = bh / H_TOT, h = bh % H_TOT;
    const int t = blockIdx.x * 512 + threadIdx.x;

    for (int i = threadIdx.x; i < 4096; i += 512) ((float4*)V1s)[i] = ((const float4*)V1w)[i];
    for (int i = threadIdx.x; i < 16384; i += 512) {
        int dd = i >> 8, j = i & 255;
        V2t[j * 66 + dd] = V2w[i];
    }
    if (threadIdx.x < 256) sV1b[threadIdx.x] = V1b[threadIdx.x];
    if (threadIdx.x < 64)  sV2b[threadIdx.x] = V2b[threadIdx.x];
    __syncthreads();

    const int o = bh * T_LEN + t;
    const int4 ti = g_topi[o];
    const float4 pw = g_topw[o];
    const float psink = g_psink[o];

    // marker from split k rows (value = hi + lo)
    float mkv[64];
    {
        const float2* kp0 = &g_k2[((size_t)bh * T_LEN + ti.x) * DH];
        const float2* kp1 = &g_k2[((size_t)bh * T_LEN + ti.y) * DH];
        const float2* kp2 = &g_k2[((size_t)bh * T_LEN + ti.z) * DH];
        const float2* kp3 = &g_k2[((size_t)bh * T_LEN + ti.w) * DH];
#pragma unroll
        for (int d = 0; d < 64; d++) {
            float2 a = kp0[d], c = kp1[d], e = kp2[d], f = kp3[d];
            mkv[d] = pw.x * (a.x + a.y) + pw.y * (c.x + c.y)
                   + pw.z * (e.x + e.y) + pw.w * (f.x + f.y);
        }
    }
    u64 mk[32];
#pragma unroll
    for (int i = 0; i < 32; i++) mk[i] = f2pack(mkv[2 * i], mkv[2 * i + 1]);

    u64 out2[32];
#pragma unroll
    for (int i = 0; i < 32; i++) out2[i] = *(const u64*)&sV2b[2 * i];

    for (int j = 0; j < 256; ++j) {
        const ulonglong2* v1 = (const ulonglong2*)(V1s + j * 64);
        u64 z0 = 0ull, z1 = 0ull, z2 = 0ull, z3 = 0ull;
#pragma unroll
        for (int i = 0; i < 16; i += 2) {
            ulonglong2 va = v1[i];
            ulonglong2 vb = v1[i + 1];
            z0 = f2fma(mk[2 * i],     va.x, z0);
            z1 = f2fma(mk[2 * i + 1], va.y, z1);
            z2 = f2fma(mk[2 * i + 2], vb.x, z2);
            z3 = f2fma(mk[2 * i + 3], vb.y, z3);
        }
        float z = ((f2sum(z0) + f2sum(z1)) + (f2sum(z2) + f2sum(z3))) + sV1b[j];
        float gl = 0.5f * z * (1.0f + erff(z * 0.70710678118f));
        u64 g2 = f2pack(gl, gl);
        const u64* v2 = (const u64*)(V2t + j * 66);
#pragma unroll
        for (int i = 0; i < 32; i++) out2[i] = f2fma(g2, v2[i], out2[i]);
    }

    const int br = h / 12, hj = h % 12;
    float* outp = &g_ctx[((size_t)(b * T_LEN + t)) * NQ + br * D_MODEL + hj * 64];
    const float* vn = vnull + h * 64;
#pragma unroll
    for (int i = 0; i < 32; i++) {
        float2 v = f2unpack(out2[i]);
        v.x = fmaf(psink, vn[2 * i], v.x);
        v.y = fmaf(psink, vn[2 * i + 1], v.y);
        ((float2*)outp)[i] = v;
    }
}

// ================= launcher =================
extern "C" void kernel_launch(void* const* d_in, const int* in_sizes, int n_in,
                              void* d_out, int out_size) {
    const float* A      = (const float*)d_in[0];
    const float* X      = (const float*)d_in[1];
    const float* WKw    = (const float*)d_in[2];
    const float* WKb    = (const float*)d_in[3];
    const float* WQw    = (const float*)d_in[4];
    const float* wedgeA = (const float*)d_in[5];
    const float* wbias  = (const float*)d_in[6];
    const float* sink   = (const float*)d_in[7];
    const float* vnull  = (const float*)d_in[8];
    const float* V1w    = (const float*)d_in[9];
    const float* V1b    = (const float*)d_in[10];
    const float* V2w    = (const float*)d_in[11];
    const float* V2b    = (const float*)d_in[12];
    const float* WOw    = (const float*)d_in[13];
    const float* WOb    = (const float*)d_in[14];
    float* Y = (float*)d_out;

    const int attn1_smem = 128 * 65 * 4 + 64 * 66 * 8;   // 33280 + 33792 = 67072
    cudaFuncSetAttribute(attn1_kernel, cudaFuncAttributeMaxDynamicSharedMemorySize, attn1_smem);
    cudaFuncSetAttribute(attn2_kernel, cudaFuncAttributeMaxDynamicSharedMemorySize, 133120);

    // 1) weights prep
    prep_w<<<3456, 256>>>(WQw, WKw, WKb, wedgeA, wbias, WOw);
    // 2) rope table
    ropetab_kernel<<<128, 256>>>();
    // 3) Q+K projections + rope + split   (z=0: Q from A, z=1: K from X)
    gemm_tf32_kernel<0><<<dim3(48, 16, 2), 256>>>(A, X, 768, nullptr, nullptr);
    // 4) attention scores / softmax / top-4   (<- ncu capture slot)
    attn1_kernel<<<dim3(8, 96), 256, attn1_smem>>>(sink);
    // 5) marker + MLP + sink
    attn2_kernel<<<dim3(2, 96), 512, 133120>>>(vnull, V1w, V1b, V2w, V2b);
    // 6) output projection
    gemm_tf32_kernel<2><<<dim3(12, 16, 1), 256>>>(nullptr, nullptr, 3072, WOb, Y);
}

// round 8
// speedup vs baseline: 1.3114x; 1.3114x over previous
#include <cuda_runtime.h>
#include <math.h>
#include <math_constants.h>

#define D_MODEL 768
#define N_BR    4
#define DH      64
#define H_TOT   48
#define BATCH   2
#define T_LEN   1024
#define M_ROWS  2048
#define NQ      3072

typedef unsigned long long u64;
typedef unsigned int u32;

// ---- packed fp32x2 helpers ----
__device__ __forceinline__ u64 f2fma(u64 a, u64 b, u64 c) {
    u64 d; asm("fma.rn.f32x2 %0, %1, %2, %3;" : "=l"(d) : "l"(a), "l"(b), "l"(c)); return d;
}
__device__ __forceinline__ u64 f2pack(float lo, float hi) {
    u64 d; asm("mov.b64 %0, {%1, %2};" : "=l"(d) : "f"(lo), "f"(hi)); return d;
}
__device__ __forceinline__ float2 f2unpack(u64 a) {
    float lo, hi; asm("mov.b64 {%0, %1}, %2;" : "=f"(lo), "=f"(hi) : "l"(a)); return make_float2(lo, hi);
}
__device__ __forceinline__ float f2sum(u64 a) { float2 v = f2unpack(a); return v.x + v.y; }

// ---- tf32 split ----
__device__ __forceinline__ float2 tf32split(float x) {
    u32 hb; asm("cvt.rna.tf32.f32 %0, %1;" : "=r"(hb) : "f"(x));
    float hf = __uint_as_float(hb);
    float lo = x - hf;
    u32 lb; asm("cvt.rna.tf32.f32 %0, %1;" : "=r"(lb) : "f"(lo));
    return make_float2(hf, __uint_as_float(lb));
}

#define MMA_TF32(ACC, A0, A1, A2, A3, B0, B1)                                        \
    asm volatile("mma.sync.aligned.m16n8k8.row.col.f32.tf32.tf32.f32 "               \
                 "{%0,%1,%2,%3}, {%4,%5,%6,%7}, {%8,%9}, {%0,%1,%2,%3};"             \
                 : "+f"(ACC[0]), "+f"(ACC[1]), "+f"(ACC[2]), "+f"(ACC[3])            \
                 : "r"(A0), "r"(A1), "r"(A2), "r"(A3), "r"(B0), "r"(B1))

// ---- scratch ----
__device__ float  g_wq2f[NQ * D_MODEL];        // folded WQ
__device__ float  g_wk2f[NQ * D_MODEL];        // folded WK (48 head-variants)
__device__ float  g_bk2 [NQ];                  // folded K bias
__device__ float  g_wotf[D_MODEL * NQ];        // WO as [n][br*768+c]
__device__ float  g_qf  [(size_t)M_ROWS * NQ]; // q roped [bh][t][d]
__device__ float  g_kf  [(size_t)M_ROWS * NQ]; // k roped
__device__ float  g_ctx [(size_t)M_ROWS * NQ]; // [b*1024+t][br*768+c]
__device__ float  g_part[(size_t)N_BR * M_ROWS * D_MODEL];  // split-K partials
__device__ float2 g_ropetab[T_LEN * 32];
__device__ int4   g_topi [BATCH * H_TOT * T_LEN];
__device__ float4 g_topw [BATCH * H_TOT * T_LEN];
__device__ float  g_psink[BATCH * H_TOT * T_LEN];

// ================= prep_w: fold wedge into WQ/WK (+bias), relayout WO ============
__global__ __launch_bounds__(256) void prep_w(const float* __restrict__ WQw,
                                              const float* __restrict__ WKw,
                                              const float* __restrict__ WKb,
                                              const float* __restrict__ wedgeA,
                                              const float* __restrict__ wbias,
                                              const float* __restrict__ WOw) {
    __shared__ float sk[4096];
    __shared__ float Ws[64 * 68];
    __shared__ float tile[32][33];
    const int blk = blockIdx.x, tid = threadIdx.x;

    if (blk < 1152) {
        const bool isK = blk >= 576;
        const int b2 = isK ? blk - 576 : blk;
        const int h = b2 / 12, c0 = (b2 % 12) * 64;
        const int hs = isK ? (h % 12) : h;
        const float* Wsrc = isK ? WKw : WQw;
        for (int i = tid; i < 4096; i += 256) {
            int e = i >> 6, d = i & 63;
            sk[i] = wedgeA[e * 64 + d] - wedgeA[d * 64 + e];
        }
        for (int i = tid; i < 4096; i += 256) {
            int e = i >> 6, c = i & 63;
            Ws[e * 68 + c] = Wsrc[(size_t)(hs * 64 + e) * D_MODEL + c0 + c];
        }
        __syncthreads();
        const int d = tid >> 2, cg = (tid & 3) * 16;
        float outv[16];
        const float bd = 1.0f + wbias[h * 64 + d];
#pragma unroll
        for (int u = 0; u < 16; u++) outv[u] = bd * Ws[d * 68 + cg + u];
        for (int e = 0; e < 64; ++e) {
            float s = sk[e * 64 + d];
            const float* wr = &Ws[e * 68 + cg];
#pragma unroll
            for (int u = 0; u < 16; u++) outv[u] = fmaf(s, wr[u], outv[u]);
        }
        float* dst = (isK ? g_wk2f : g_wq2f) + (size_t)(h * 64 + d) * D_MODEL + c0 + cg;
#pragma unroll
        for (int u = 0; u < 16; u++) dst[u] = outv[u];

        if (isK && c0 == 0 && tid < 64) {
            float acc = (1.0f + wbias[h * 64 + tid]) * WKb[hs * 64 + tid];
            for (int s = 0; s < 64; ++s) acc += sk[s * 64 + tid] * WKb[hs * 64 + s];
            g_bk2[h * 64 + tid] = acc;
        }
    } else {
        const int b3 = blk - 1152;
        const int br = b3 / 576, rem = b3 % 576;
        const int cb = (rem / 24) * 32, nb = (rem % 24) * 32;
        const int tx = tid & 31, ty = tid >> 5;
        for (int r = ty; r < 32; r += 8)
            tile[r][tx] = WOw[((size_t)br * D_MODEL + cb + r) * D_MODEL + nb + tx];
        __syncthreads();
        for (int r = ty; r < 32; r += 8)
            g_wotf[(size_t)(nb + r) * NQ + br * D_MODEL + cb + tx] = tile[tx][r];
    }
}

// ================= rope table =================
__global__ void ropetab_kernel() {
    int idx = blockIdx.x * 256 + threadIdx.x;
    int t = idx >> 5, i = idx & 31;
    float inv = exp2f(-(float)i * 0.41524101186092034f);
    float fr = (float)t * inv;
    g_ropetab[idx] = make_float2(cosf(fr), sinf(fr));
}

// ================= tf32-3x NT GEMM (R4 style, in-loop split staging) =============
// MODE 0: z=0: A0 @ wq2f -> rope -> g_qf ; z=1: A1 @ wk2f + bk2 -> rope -> g_kf
// MODE 2: z=br: ctx[:, br*768:] @ wotf[:, br*768:]^T (K=768) -> g_part[br]
template <int MODE>
__global__ __launch_bounds__(256) void gemm_tf32_kernel(const float* __restrict__ A0,
                                                        const float* __restrict__ A1,
                                                        int K) {
    __shared__ float2 As2[16 * 132];
    __shared__ float2 Bs2[16 * 68];

    const int tid = threadIdx.x;
    const int m0 = blockIdx.y * 128, n0 = blockIdx.x * 64;
    const int warpId = tid >> 5, lane = tid & 31;
    const int warpM = warpId & 3, warpN = warpId >> 2;
    const int g = lane >> 2, tg = lane & 3;
    const int sa_m = tid >> 1, sa_k = (tid & 1) * 8;
    const int sb_n = tid & 63, sb_k = (tid >> 6) * 4;

    const float* Aop;
    const float* Bop;
    int ldA, ldB;
    if (MODE == 0) {
        Aop = blockIdx.z ? A1 : A0;
        Bop = blockIdx.z ? g_wk2f : g_wq2f;
        ldA = 768; ldB = 768;
    } else {
        Aop = g_ctx  + blockIdx.z * 768;
        Bop = g_wotf + blockIdx.z * 768;
        ldA = 3072; ldB = 3072;
    }

    float acc[2][4][4];
#pragma unroll
    for (int mf = 0; mf < 2; mf++)
#pragma unroll
        for (int nf = 0; nf < 4; nf++)
#pragma unroll
            for (int r = 0; r < 4; r++) acc[mf][nf][r] = 0.f;

    const float* Arow = Aop + (size_t)(m0 + sa_m) * ldA + sa_k;
    const float* Brow = Bop + (size_t)(n0 + sb_n) * ldB + sb_k;

    float4 pa0 = *(const float4*)(Arow);
    float4 pa1 = *(const float4*)(Arow + 4);
    float4 pb  = *(const float4*)(Brow);

    for (int k0 = 0; k0 < K; k0 += 16) {
        __syncthreads();
        {
            float av[8] = {pa0.x, pa0.y, pa0.z, pa0.w, pa1.x, pa1.y, pa1.z, pa1.w};
#pragma unroll
            for (int j = 0; j < 8; j++) As2[(sa_k + j) * 132 + sa_m] = tf32split(av[j]);
            float bv[4] = {pb.x, pb.y, pb.z, pb.w};
#pragma unroll
            for (int j = 0; j < 4; j++) Bs2[(sb_k + j) * 68 + sb_n] = tf32split(bv[j]);
        }
        __syncthreads();
        if (k0 + 16 < K) {
            pa0 = *(const float4*)(Arow + k0 + 16);
            pa1 = *(const float4*)(Arow + k0 + 20);
            pb  = *(const float4*)(Brow + k0 + 16);
        }
#pragma unroll
        for (int ks = 0; ks < 16; ks += 8) {
            float2 fa[2][4];
#pragma unroll
            for (int mf = 0; mf < 2; mf++) {
                const int rI = warpM * 32 + mf * 16 + g;
                const float2* c0p = &As2[(ks + tg) * 132];
                const float2* c4p = &As2[(ks + tg + 4) * 132];
                fa[mf][0] = c0p[rI];
                fa[mf][1] = c0p[rI + 8];
                fa[mf][2] = c4p[rI];
                fa[mf][3] = c4p[rI + 8];
            }
            float2 fb[4][2];
#pragma unroll
            for (int nf = 0; nf < 4; nf++) {
                const int cI = warpN * 32 + nf * 8 + g;
                fb[nf][0] = Bs2[(ks + tg) * 68 + cI];
                fb[nf][1] = Bs2[(ks + tg + 4) * 68 + cI];
            }
#pragma unroll
            for (int mf = 0; mf < 2; mf++) {
                const u32 ah0 = __float_as_uint(fa[mf][0].x), al0 = __float_as_uint(fa[mf][0].y);
                const u32 ah1 = __float_as_uint(fa[mf][1].x), al1 = __float_as_uint(fa[mf][1].y);
                const u32 ah2 = __float_as_uint(fa[mf][2].x), al2 = __float_as_uint(fa[mf][2].y);
                const u32 ah3 = __float_as_uint(fa[mf][3].x), al3 = __float_as_uint(fa[mf][3].y);
#pragma unroll
                for (int nf = 0; nf < 4; nf++) {
                    const u32 bh0 = __float_as_uint(fb[nf][0].x), bl0 = __float_as_uint(fb[nf][0].y);
                    const u32 bh1 = __float_as_uint(fb[nf][1].x), bl1 = __float_as_uint(fb[nf][1].y);
                    MMA_TF32(acc[mf][nf], al0, al1, al2, al3, bh0, bh1);
                    MMA_TF32(acc[mf][nf], ah0, ah1, ah2, ah3, bl0, bl1);
                    MMA_TF32(acc[mf][nf], ah0, ah1, ah2, ah3, bh0, bh1);
                }
            }
        }
    }

    // ---- epilogue ----
#pragma unroll
    for (int mf = 0; mf < 2; mf++) {
#pragma unroll
        for (int nf = 0; nf < 4; nf++) {
            const int r0 = m0 + warpM * 32 + mf * 16 + g;
            const int r1 = r0 + 8;
            float c0 = acc[mf][nf][0], c1 = acc[mf][nf][1];
            float c2 = acc[mf][nf][2], c3 = acc[mf][nf][3];
            if (MODE == 0) {
                const int h = blockIdx.x;
                const int i = warpN * 16 + nf * 4 + tg;     // rope pair index
                float* dstbase = blockIdx.z ? g_kf : g_qf;
                if (blockIdx.z) {
                    const float b0 = g_bk2[h * 64 + 2 * i];
                    const float b1 = g_bk2[h * 64 + 2 * i + 1];
                    c0 += b0; c1 += b1; c2 += b0; c3 += b1;
                }
                {
                    const int t = r0 & 1023, bb = r0 >> 10;
                    float2 rc = g_ropetab[t * 32 + i];
                    float* qp = &dstbase[(((size_t)(bb * H_TOT + h)) * T_LEN + t) * DH];
                    qp[i]      = c0 * rc.x - c1 * rc.y;
                    qp[i + 32] = c0 * rc.y + c1 * rc.x;
                }
                {
                    const int t = r1 & 1023, bb = r1 >> 10;
                    float2 rc = g_ropetab[t * 32 + i];
                    float* qp = &dstbase[(((size_t)(bb * H_TOT + h)) * T_LEN + t) * DH];
                    qp[i]      = c2 * rc.x - c3 * rc.y;
                    qp[i + 32] = c2 * rc.y + c3 * rc.x;
                }
            } else {
                const int nc = n0 + warpN * 32 + nf * 8 + 2 * tg;
                float* base = g_part + (size_t)blockIdx.z * M_ROWS * D_MODEL;
                *(float2*)&base[(size_t)r0 * 768 + nc] = make_float2(c0, c1);
                *(float2*)&base[(size_t)r1 * 768 + nc] = make_float2(c2, c3);
            }
        }
    }
}

// ================= reduce: Y = 0.25*sum_br part + 0.25*sum_br WOb ================
__global__ __launch_bounds__(256) void reduce_kernel(const float* __restrict__ WOb,
                                                     float* __restrict__ Y) {
    const size_t i4 = (size_t)blockIdx.x * 256 + threadIdx.x;    // float4 index
    const size_t base = i4 * 4;
    const int nc = (int)(base % 768);
    float4 p0 = *(const float4*)&g_part[base];
    float4 p1 = *(const float4*)&g_part[base + (size_t)M_ROWS * D_MODEL];
    float4 p2 = *(const float4*)&g_part[base + (size_t)2 * M_ROWS * D_MODEL];
    float4 p3 = *(const float4*)&g_part[base + (size_t)3 * M_ROWS * D_MODEL];
    float4 o;
    o.x = 0.25f * (p0.x + p1.x + p2.x + p3.x) + 0.25f * (WOb[nc]     + WOb[768 + nc]     + WOb[1536 + nc]     + WOb[2304 + nc]);
    o.y = 0.25f * (p0.y + p1.y + p2.y + p3.y) + 0.25f * (WOb[nc + 1] + WOb[768 + nc + 1] + WOb[1536 + nc + 1] + WOb[2304 + nc + 1]);
    o.z = 0.25f * (p0.z + p1.z + p2.z + p3.z) + 0.25f * (WOb[nc + 2] + WOb[768 + nc + 2] + WOb[1536 + nc + 2] + WOb[2304 + nc + 2]);
    o.w = 0.25f * (p0.w + p1.w + p2.w + p3.w) + 0.25f * (WOb[nc + 3] + WOb[768 + nc + 3] + WOb[1536 + nc + 3] + WOb[2304 + nc + 3]);
    *(float4*)&Y[base] = o;
}

// ---- online softmax + top-4 update (one stream) ----
#define SMTK_UPDATE(sc, sidx, mrun, lrun, s0v, s1v, s2v, s3v, i0v, i1v, i2v, i3v) \
    do {                                                                          \
        if ((sc) <= (mrun)) { (lrun) += __expf((sc) - (mrun)); }                  \
        else { (lrun) = fmaf((lrun), __expf((mrun) - (sc)), 1.0f); (mrun) = (sc); } \
        if ((sc) > (s3v)) {                                                       \
            if ((sc) > (s2v)) {                                                   \
                (s3v) = (s2v); (i3v) = (i2v);                                     \
                if ((sc) > (s1v)) {                                               \
                    (s2v) = (s1v); (i2v) = (i1v);                                 \
                    if ((sc) > (s0v)) {                                           \
                        (s1v) = (s0v); (i1v) = (i0v);                             \
                        (s0v) = (sc); (i0v) = (sidx);                             \
                    } else { (s1v) = (sc); (i1v) = (sidx); }                      \
                } else { (s2v) = (sc); (i2v) = (sidx); }                          \
            } else { (s3v) = (sc); (i3v) = (sidx); }                              \
        }                                                                         \
    } while (0)

// ================= attn1: dual-row scalar scores + softmax + top-4 ===============
// CTA: 128 thr, covers 256 t-rows of one bh. Thread: rows tA=t0+tid, tB=tA+128.
// K staged in 128-row tiles (32 KB smem). Shared K broadcast feeds both rows.
__global__ __launch_bounds__(128) void attn1_kernel(const float* __restrict__ sink) {
    extern __shared__ float ks[];            // 128*64 floats
    const int bh = blockIdx.y, h = bh % H_TOT;
    const int xt = (gridDim.x - 1) - blockIdx.x;   // heavy tiles first
    const int t0 = xt * 256;
    const int tid = threadIdx.x;
    const int tA = t0 + tid;
    const int tB = tA + 128;

    u64 qA[32], qB[32];
    {
        const ulonglong2* pa = (const ulonglong2*)&g_qf[((size_t)bh * T_LEN + tA) * DH];
        const ulonglong2* pb = (const ulonglong2*)&g_qf[((size_t)bh * T_LEN + tB) * DH];
#pragma unroll
        for (int i = 0; i < 16; i++) {
            ulonglong2 va = pa[i]; qA[2 * i] = va.x; qA[2 * i + 1] = va.y;
            ulonglong2 vb = pb[i]; qB[2 * i] = vb.x; qB[2 * i + 1] = vb.y;
        }
    }

    float mA = -CUDART_INF_F, lA = 0.f, mB = -CUDART_INF_F, lB = 0.f;
    float sA0 = -CUDART_INF_F, sA1 = -CUDART_INF_F, sA2 = -CUDART_INF_F, sA3 = -CUDART_INF_F;
    float sB0 = -CUDART_INF_F, sB1 = -CUDART_INF_F, sB2 = -CUDART_INF_F, sB3 = -CUDART_INF_F;
    int iA0 = 0, iA1 = 0, iA2 = 0, iA3 = 0;
    int iB0 = 0, iB1 = 0, iB2 = 0, iB3 = 0;

    for (int s0 = 0; s0 <= t0 + 128; s0 += 128) {
        __syncthreads();
        {
            const float4* kg = (const float4*)&g_kf[((size_t)bh * T_LEN + s0) * DH];
            float4* d4 = (float4*)ks;
            for (int i = tid; i < 2048; i += 128) d4[i] = kg[i];
        }
        __syncthreads();

        if (s0 < t0) {
            // full dual tile: both rows take all 128 scores
            for (int s = s0; s < s0 + 128; ++s) {
                const u64* kr = (const u64*)(ks + (s - s0) * DH);
                u64 a0 = 0ull, a1 = 0ull, a2 = 0ull, a3 = 0ull;
                u64 b0 = 0ull, b1 = 0ull, b2 = 0ull, b3 = 0ull;
#pragma unroll
                for (int i = 0; i < 32; i += 4) {
                    u64 k0 = kr[i], k1 = kr[i + 1], k2 = kr[i + 2], k3 = kr[i + 3];
                    a0 = f2fma(qA[i],     k0, a0);  b0 = f2fma(qB[i],     k0, b0);
                    a1 = f2fma(qA[i + 1], k1, a1);  b1 = f2fma(qB[i + 1], k1, b1);
                    a2 = f2fma(qA[i + 2], k2, a2);  b2 = f2fma(qB[i + 2], k2, b2);
                    a3 = f2fma(qA[i + 3], k3, a3);  b3 = f2fma(qB[i + 3], k3, b3);
                }
                float scA = ((f2sum(a0) + f2sum(a1)) + (f2sum(a2) + f2sum(a3))) * 0.125f;
                float scB = ((f2sum(b0) + f2sum(b1)) + (f2sum(b2) + f2sum(b3))) * 0.125f;
                SMTK_UPDATE(scA, s, mA, lA, sA0, sA1, sA2, sA3, iA0, iA1, iA2, iA3);
                SMTK_UPDATE(scB, s, mB, lB, sB0, sB1, sB2, sB3, iB0, iB1, iB2, iB3);
            }
        } else if (s0 == t0) {
            // diagonal tile for row A (A guarded), full for row B
            for (int s = s0; s < s0 + 128; ++s) {
                const u64* kr = (const u64*)(ks + (s - s0) * DH);
                u64 a0 = 0ull, a1 = 0ull, a2 = 0ull, a3 = 0ull;
                u64 b0 = 0ull, b1 = 0ull, b2 = 0ull, b3 = 0ull;
#pragma unroll
                for (int i = 0; i < 32; i += 4) {
                    u64 k0 = kr[i], k1 = kr[i + 1], k2 = kr[i + 2], k3 = kr[i + 3];
                    a0 = f2fma(qA[i],     k0, a0);  b0 = f2fma(qB[i],     k0, b0);
                    a1 = f2fma(qA[i + 1], k1, a1);  b1 = f2fma(qB[i + 1], k1, b1);
                    a2 = f2fma(qA[i + 2], k2, a2);  b2 = f2fma(qB[i + 2], k2, b2);
                    a3 = f2fma(qA[i + 3], k3, a3);  b3 = f2fma(qB[i + 3], k3, b3);
                }
                float scB = ((f2sum(b0) + f2sum(b1)) + (f2sum(b2) + f2sum(b3))) * 0.125f;
                SMTK_UPDATE(scB, s, mB, lB, sB0, sB1, sB2, sB3, iB0, iB1, iB2, iB3);
                if (s <= tA) {
                    float scA = ((f2sum(a0) + f2sum(a1)) + (f2sum(a2) + f2sum(a3))) * 0.125f;
                    SMTK_UPDATE(scA, s, mA, lA, sA0, sA1, sA2, sA3, iA0, iA1, iA2, iA3);
                }
            }
        } else {
            // tail tile: row B only, s up to tB
            const int sMax = tB;
            for (int s = s0; s <= sMax; ++s) {
                const u64* kr = (const u64*)(ks + (s - s0) * DH);
                u64 b0 = 0ull, b1 = 0ull, b2 = 0ull, b3 = 0ull;
#pragma unroll
                for (int i = 0; i < 32; i += 4) {
                    u64 k0 = kr[i], k1 = kr[i + 1], k2 = kr[i + 2], k3 = kr[i + 3];
                    b0 = f2fma(qB[i],     k0, b0);
                    b1 = f2fma(qB[i + 1], k1, b1);
                    b2 = f2fma(qB[i + 2], k2, b2);
                    b3 = f2fma(qB[i + 3], k3, b3);
                }
                float scB = ((f2sum(b0) + f2sum(b1)) + (f2sum(b2) + f2sum(b3))) * 0.125f;
                SMTK_UPDATE(scB, s, mB, lB, sB0, sB1, sB2, sB3, iB0, iB1, iB2, iB3);
            }
        }
    }

    // finalize both rows
    const float skv = sink[h];
    {
        const float mf = fmaxf(mA, skv);
        const float Z = lA * __expf(mA - mf) + __expf(skv - mf);
        const float invZ = 1.0f / Z;
        float p0 = __expf(sA0 - mf) * invZ;
        float p1 = __expf(sA1 - mf) * invZ;
        float p2 = __expf(sA2 - mf) * invZ;
        float p3 = __expf(sA3 - mf) * invZ;
        const float winv = 1.0f / (p0 + p1 + p2 + p3 + 1e-9f);
        const int o = bh * T_LEN + tA;
        g_topi[o]  = make_int4(iA0, iA1, iA2, iA3);
        g_topw[o]  = make_float4(p0 * winv, p1 * winv, p2 * winv, p3 * winv);
        g_psink[o] = __expf(skv - mf) * invZ;
    }
    {
        const float mf = fmaxf(mB, skv);
        const float Z = lB * __expf(mB - mf) + __expf(skv - mf);
        const float invZ = 1.0f / Z;
        float p0 = __expf(sB0 - mf) * invZ;
        float p1 = __expf(sB1 - mf) * invZ;
        float p2 = __expf(sB2 - mf) * invZ;
        float p3 = __expf(sB3 - mf) * invZ;
        const float winv = 1.0f / (p0 + p1 + p2 + p3 + 1e-9f);
        const int o = bh * T_LEN + tB;
        g_topi[o]  = make_int4(iB0, iB1, iB2, iB3);
        g_topw[o]  = make_float4(p0 * winv, p1 * winv, p2 * winv, p3 * winv);
        g_psink[o] = __expf(skv - mf) * invZ;
    }
}

// ================= attn2: marker gather + MLP + ctx write (256 thr, no spills) ===
__global__ __launch_bounds__(256) void attn2_kernel(const float* __restrict__ vnull,
                                                    const float* __restrict__ V1w,
                                                    const float* __restrict__ V1b,
                                                    const float* __restrict__ V2w,
                                                    const float* __restrict__ V2b) {
    extern __shared__ float sm2[];
    float* V1s = sm2;                 // 16384
    float* V2t = sm2 + 16384;         // 256*66
    __shared__ float sV1b[256];
    __shared__ float sV2b[64];

    const int bh = blockIdx.y, b = bh / H_TOT, h = bh % H_TOT;
    const int t = blockIdx.x * 256 + threadIdx.x;

    for (int i = threadIdx.x; i < 4096; i += 256) ((float4*)V1s)[i] = ((const float4*)V1w)[i];
    for (int i = threadIdx.x; i < 16384; i += 256) {
        int dd = i >> 8, j = i & 255;
        V2t[j * 66 + dd] = V2w[i];
    }
    if (threadIdx.x < 256) sV1b[threadIdx.x] = V1b[threadIdx.x];
    if (threadIdx.x < 64)  sV2b[threadIdx.x] = V2b[threadIdx.x];
    __syncthreads();

    const int o = bh * T_LEN + t;
    const int4 ti = g_topi[o];
    const float4 pw = g_topw[o];
    const float psink = g_psink[o];

    u64 mk[32];
    {
        const float4* kp0 = (const float4*)&g_kf[((size_t)bh * T_LEN + ti.x) * DH];
        const float4* kp1 = (const float4*)&g_kf[((size_t)bh * T_LEN + ti.y) * DH];
        const float4* kp2 = (const float4*)&g_kf[((size_t)bh * T_LEN + ti.z) * DH];
        const float4* kp3 = (const float4*)&g_kf[((size_t)bh * T_LEN + ti.w) * DH];
#pragma unroll
        for (int i = 0; i < 16; i++) {
            float4 a = kp0[i], c = kp1[i], e = kp2[i], f = kp3[i];
            float v0 = pw.x * a.x + pw.y * c.x + pw.z * e.x + pw.w * f.x;
            float v1 = pw.x * a.y + pw.y * c.y + pw.z * e.y + pw.w * f.y;
            float v2 = pw.x * a.z + pw.y * c.z + pw.z * e.z + pw.w * f.z;
            float v3 = pw.x * a.w + pw.y * c.w + pw.z * e.w + pw.w * f.w;
            mk[2 * i]     = f2pack(v0, v1);
            mk[2 * i + 1] = f2pack(v2, v3);
        }
    }

    u64 out2[32];
#pragma unroll
    for (int i = 0; i < 32; i++) out2[i] = *(const u64*)&sV2b[2 * i];

    for (int j = 0; j < 256; ++j) {
        const ulonglong2* v1 = (const ulonglong2*)(V1s + j * 64);
        u64 z0 = 0ull, z1 = 0ull, z2 = 0ull, z3 = 0ull;
#pragma unroll
        for (int i = 0; i < 16; i += 2) {
            ulonglong2 va = v1[i];
            ulonglong2 vb = v1[i + 1];
            z0 = f2fma(mk[2 * i],     va.x, z0);
            z1 = f2fma(mk[2 * i + 1], va.y, z1);
            z2 = f2fma(mk[2 * i + 2], vb.x, z2);
            z3 = f2fma(mk[2 * i + 3], vb.y, z3);
        }
        float z = ((f2sum(z0) + f2sum(z1)) + (f2sum(z2) + f2sum(z3))) + sV1b[j];
        float gl = 0.5f * z * (1.0f + erff(z * 0.70710678118f));
        u64 g2 = f2pack(gl, gl);
        const u64* v2 = (const u64*)(V2t + j * 66);
#pragma unroll
        for (int i = 0; i < 32; i++) out2[i] = f2fma(g2, v2[i], out2[i]);
    }

    const int br = h / 12, hj = h % 12;
    float* outp = &g_ctx[((size_t)(b * T_LEN + t)) * NQ + br * D_MODEL + hj * 64];
    const float* vn = vnull + h * 64;
#pragma unroll
    for (int i = 0; i < 32; i++) {
        float2 v = f2unpack(out2[i]);
        v.x = fmaf(psink, vn[2 * i], v.x);
        v.y = fmaf(psink, vn[2 * i + 1], v.y);
        ((float2*)outp)[i] = v;
    }
}

// ================= launcher =================
extern "C" void kernel_launch(void* const* d_in, const int* in_sizes, int n_in,
                              void* d_out, int out_size) {
    const float* A      = (const float*)d_in[0];
    const float* X      = (const float*)d_in[1];
    const float* WKw    = (const float*)d_in[2];
    const float* WKb    = (const float*)d_in[3];
    const float* WQw    = (const float*)d_in[4];
    const float* wedgeA = (const float*)d_in[5];
    const float* wbias  = (const float*)d_in[6];
    const float* sink   = (const float*)d_in[7];
    const float* vnull  = (const float*)d_in[8];
    const float* V1w    = (const float*)d_in[9];
    const float* V1b    = (const float*)d_in[10];
    const float* V2w    = (const float*)d_in[11];
    const float* V2b    = (const float*)d_in[12];
    const float* WOw    = (const float*)d_in[13];
    const float* WOb    = (const float*)d_in[14];
    float* Y = (float*)d_out;

    cudaFuncSetAttribute(attn1_kernel, cudaFuncAttributeMaxDynamicSharedMemorySize, 32768);
    cudaFuncSetAttribute(attn2_kernel, cudaFuncAttributeMaxDynamicSharedMemorySize, 133120);

    // 1) weights prep (fold wedge into WQ/WK, WO relayout)
    prep_w<<<3456, 256>>>(WQw, WKw, WKb, wedgeA, wbias, WOw);
    // 2) rope table
    ropetab_kernel<<<128, 256>>>();
    // 3) Q+K projections + rope  (z=0: Q from A, z=1: K from X)
    gemm_tf32_kernel<0><<<dim3(48, 16, 2), 256>>>(A, X, 768);
    // 4) attention scores / softmax / top-4  (<- ncu capture slot)
    attn1_kernel<<<dim3(4, 96), 128, 32768>>>(sink);
    // 5) marker + MLP + sink
    attn2_kernel<<<dim3(4, 96), 256, 133120>>>(vnull, V1w, V1b, V2w, V2b);
    // 6) output projection, split-K over branches
    gemm_tf32_kernel<2><<<dim3(12, 16, 4), 256>>>(nullptr, nullptr, 768);
    // 7) combine partials + bias
    reduce_kernel<<<1536, 256>>>(WOb, Y);
}

// round 9
// speedup vs baseline: 1.4265x; 1.0877x over previous
#include <cuda_runtime.h>
#include <math.h>
#include <math_constants.h>

#define D_MODEL 768
#define N_BR    4
#define DH      64
#define H_TOT   48
#define BATCH   2
#define T_LEN   1024
#define M_ROWS  2048
#define NQ      3072

typedef unsigned long long u64;
typedef unsigned int u32;

// ---- packed fp32x2 helpers ----
__device__ __forceinline__ u64 f2fma(u64 a, u64 b, u64 c) {
    u64 d; asm("fma.rn.f32x2 %0, %1, %2, %3;" : "=l"(d) : "l"(a), "l"(b), "l"(c)); return d;
}
__device__ __forceinline__ u64 f2pack(float lo, float hi) {
    u64 d; asm("mov.b64 %0, {%1, %2};" : "=l"(d) : "f"(lo), "f"(hi)); return d;
}
__device__ __forceinline__ float2 f2unpack(u64 a) {
    float lo, hi; asm("mov.b64 {%0, %1}, %2;" : "=f"(lo), "=f"(hi) : "l"(a)); return make_float2(lo, hi);
}
__device__ __forceinline__ float f2sum(u64 a) { float2 v = f2unpack(a); return v.x + v.y; }

// ---- tf32 split ----
__device__ __forceinline__ float2 tf32split(float x) {
    u32 hb; asm("cvt.rna.tf32.f32 %0, %1;" : "=r"(hb) : "f"(x));
    float hf = __uint_as_float(hb);
    float lo = x - hf;
    u32 lb; asm("cvt.rna.tf32.f32 %0, %1;" : "=r"(lb) : "f"(lo));
    return make_float2(hf, __uint_as_float(lb));
}

#define MMA_TF32(ACC, A0, A1, A2, A3, B0, B1)                                        \
    asm volatile("mma.sync.aligned.m16n8k8.row.col.f32.tf32.tf32.f32 "               \
                 "{%0,%1,%2,%3}, {%4,%5,%6,%7}, {%8,%9}, {%0,%1,%2,%3};"             \
                 : "+f"(ACC[0]), "+f"(ACC[1]), "+f"(ACC[2]), "+f"(ACC[3])            \
                 : "r"(A0), "r"(A1), "r"(A2), "r"(A3), "r"(B0), "r"(B1))

// ---- scratch ----
__device__ float  g_wq2f[NQ * D_MODEL];
__device__ float  g_wk2f[NQ * D_MODEL];
__device__ float  g_bk2 [NQ];
__device__ float  g_wotf[D_MODEL * NQ];
__device__ float  g_qf  [(size_t)M_ROWS * NQ];
__device__ float  g_kf  [(size_t)M_ROWS * NQ];
__device__ float  g_ctx [(size_t)M_ROWS * NQ];
__device__ float  g_part[(size_t)N_BR * M_ROWS * D_MODEL];
__device__ float2 g_ropetab[T_LEN * 32];
__device__ int4   g_topi [BATCH * H_TOT * T_LEN];
__device__ float4 g_topw [BATCH * H_TOT * T_LEN];
__device__ float  g_psink[BATCH * H_TOT * T_LEN];

// ================= prep_w =================
__global__ __launch_bounds__(256) void prep_w(const float* __restrict__ WQw,
                                              const float* __restrict__ WKw,
                                              const float* __restrict__ WKb,
                                              const float* __restrict__ wedgeA,
                                              const float* __restrict__ wbias,
                                              const float* __restrict__ WOw) {
    __shared__ float sk[4096];
    __shared__ float Ws[64 * 68];
    __shared__ float tile[32][33];
    const int blk = blockIdx.x, tid = threadIdx.x;

    if (blk < 1152) {
        const bool isK = blk >= 576;
        const int b2 = isK ? blk - 576 : blk;
        const int h = b2 / 12, c0 = (b2 % 12) * 64;
        const int hs = isK ? (h % 12) : h;
        const float* Wsrc = isK ? WKw : WQw;
        for (int i = tid; i < 4096; i += 256) {
            int e = i >> 6, d = i & 63;
            sk[i] = wedgeA[e * 64 + d] - wedgeA[d * 64 + e];
        }
        for (int i = tid; i < 4096; i += 256) {
            int e = i >> 6, c = i & 63;
            Ws[e * 68 + c] = Wsrc[(size_t)(hs * 64 + e) * D_MODEL + c0 + c];
        }
        __syncthreads();
        const int d = tid >> 2, cg = (tid & 3) * 16;
        float outv[16];
        const float bd = 1.0f + wbias[h * 64 + d];
#pragma unroll
        for (int u = 0; u < 16; u++) outv[u] = bd * Ws[d * 68 + cg + u];
        for (int e = 0; e < 64; ++e) {
            float s = sk[e * 64 + d];
            const float* wr = &Ws[e * 68 + cg];
#pragma unroll
            for (int u = 0; u < 16; u++) outv[u] = fmaf(s, wr[u], outv[u]);
        }
        float* dst = (isK ? g_wk2f : g_wq2f) + (size_t)(h * 64 + d) * D_MODEL + c0 + cg;
#pragma unroll
        for (int u = 0; u < 16; u++) dst[u] = outv[u];

        if (isK && c0 == 0 && tid < 64) {
            float acc = (1.0f + wbias[h * 64 + tid]) * WKb[hs * 64 + tid];
            for (int s = 0; s < 64; ++s) acc += sk[s * 64 + tid] * WKb[hs * 64 + s];
            g_bk2[h * 64 + tid] = acc;
        }
    } else {
        const int b3 = blk - 1152;
        const int br = b3 / 576, rem = b3 % 576;
        const int cb = (rem / 24) * 32, nb = (rem % 24) * 32;
        const int tx = tid & 31, ty = tid >> 5;
        for (int r = ty; r < 32; r += 8)
            tile[r][tx] = WOw[((size_t)br * D_MODEL + cb + r) * D_MODEL + nb + tx];
        __syncthreads();
        for (int r = ty; r < 32; r += 8)
            g_wotf[(size_t)(nb + r) * NQ + br * D_MODEL + cb + tx] = tile[tx][r];
    }
}

// ================= rope table =================
__global__ void ropetab_kernel() {
    int idx = blockIdx.x * 256 + threadIdx.x;
    int t = idx >> 5, i = idx & 31;
    float inv = exp2f(-(float)i * 0.41524101186092034f);
    float fr = (float)t * inv;
    g_ropetab[idx] = make_float2(cosf(fr), sinf(fr));
}

// ================= tf32-3x NT GEMM, double-buffered, in-loop split ===============
// MODE 0: z=0: A0 @ wq2f -> rope -> g_qf ; z=1: A1 @ wk2f + bk2 -> rope -> g_kf
// MODE 2: z=br: ctx[:, br*768:] @ wotf[:, br*768:]^T (K=768) -> g_part[br]
template <int MODE>
__global__ __launch_bounds__(256) void gemm_tf32_kernel(const float* __restrict__ A0,
                                                        const float* __restrict__ A1,
                                                        int K) {
    extern __shared__ float2 smg[];
    float2* Abuf = smg;            // 2 x 16*132
    float2* Bbuf = smg + 4224;     // 2 x 16*68

    const int tid = threadIdx.x;
    const int m0 = blockIdx.y * 128, n0 = blockIdx.x * 64;
    const int warpId = tid >> 5, lane = tid & 31;
    const int warpM = warpId & 3, warpN = warpId >> 2;
    const int g = lane >> 2, tg = lane & 3;
    const int sa_m = tid >> 1, sa_k = (tid & 1) * 8;
    const int sb_n = tid & 63, sb_k = (tid >> 6) * 4;

    const float* Aop;
    const float* Bop;
    int ldA, ldB;
    if (MODE == 0) {
        Aop = blockIdx.z ? A1 : A0;
        Bop = blockIdx.z ? g_wk2f : g_wq2f;
        ldA = 768; ldB = 768;
    } else {
        Aop = g_ctx  + blockIdx.z * 768;
        Bop = g_wotf + blockIdx.z * 768;
        ldA = 3072; ldB = 3072;
    }

    float acc[2][4][4];
#pragma unroll
    for (int mf = 0; mf < 2; mf++)
#pragma unroll
        for (int nf = 0; nf < 4; nf++)
#pragma unroll
            for (int r = 0; r < 4; r++) acc[mf][nf][r] = 0.f;

    const float* Arow = Aop + (size_t)(m0 + sa_m) * ldA + sa_k;
    const float* Brow = Bop + (size_t)(n0 + sb_n) * ldB + sb_k;

    float4 pa0 = *(const float4*)(Arow);
    float4 pa1 = *(const float4*)(Arow + 4);
    float4 pb  = *(const float4*)(Brow);

    // stage buffer 0
    {
        float av[8] = {pa0.x, pa0.y, pa0.z, pa0.w, pa1.x, pa1.y, pa1.z, pa1.w};
#pragma unroll
        for (int j = 0; j < 8; j++) Abuf[(sa_k + j) * 132 + sa_m] = tf32split(av[j]);
        float bv[4] = {pb.x, pb.y, pb.z, pb.w};
#pragma unroll
        for (int j = 0; j < 4; j++) Bbuf[(sb_k + j) * 68 + sb_n] = tf32split(bv[j]);
    }
    __syncthreads();

    int p = 0;
    for (int k0 = 0; k0 < K; k0 += 16) {
        const bool more = (k0 + 16) < K;
        if (more) {
            pa0 = *(const float4*)(Arow + k0 + 16);
            pa1 = *(const float4*)(Arow + k0 + 20);
            pb  = *(const float4*)(Brow + k0 + 16);
        }
        const float2* As2 = Abuf + p * 2112;
        const float2* Bs2 = Bbuf + p * 1088;
#pragma unroll
        for (int ks = 0; ks < 16; ks += 8) {
            float2 fa[2][4];
#pragma unroll
            for (int mf = 0; mf < 2; mf++) {
                const int rI = warpM * 32 + mf * 16 + g;
                const float2* c0p = &As2[(ks + tg) * 132];
                const float2* c4p = &As2[(ks + tg + 4) * 132];
                fa[mf][0] = c0p[rI];
                fa[mf][1] = c0p[rI + 8];
                fa[mf][2] = c4p[rI];
                fa[mf][3] = c4p[rI + 8];
            }
            float2 fb[4][2];
#pragma unroll
            for (int nf = 0; nf < 4; nf++) {
                const int cI = warpN * 32 + nf * 8 + g;
                fb[nf][0] = Bs2[(ks + tg) * 68 + cI];
                fb[nf][1] = Bs2[(ks + tg + 4) * 68 + cI];
            }
#pragma unroll
            for (int mf = 0; mf < 2; mf++) {
                const u32 ah0 = __float_as_uint(fa[mf][0].x), al0 = __float_as_uint(fa[mf][0].y);
                const u32 ah1 = __float_as_uint(fa[mf][1].x), al1 = __float_as_uint(fa[mf][1].y);
                const u32 ah2 = __float_as_uint(fa[mf][2].x), al2 = __float_as_uint(fa[mf][2].y);
                const u32 ah3 = __float_as_uint(fa[mf][3].x), al3 = __float_as_uint(fa[mf][3].y);
#pragma unroll
                for (int nf = 0; nf < 4; nf++) {
                    const u32 bh0 = __float_as_uint(fb[nf][0].x), bl0 = __float_as_uint(fb[nf][0].y);
                    const u32 bh1 = __float_as_uint(fb[nf][1].x), bl1 = __float_as_uint(fb[nf][1].y);
                    MMA_TF32(acc[mf][nf], al0, al1, al2, al3, bh0, bh1);
                    MMA_TF32(acc[mf][nf], ah0, ah1, ah2, ah3, bl0, bl1);
                    MMA_TF32(acc[mf][nf], ah0, ah1, ah2, ah3, bh0, bh1);
                }
            }
        }
        if (more) {
            float2* An = Abuf + (p ^ 1) * 2112;
            float2* Bn = Bbuf + (p ^ 1) * 1088;
            float av[8] = {pa0.x, pa0.y, pa0.z, pa0.w, pa1.x, pa1.y, pa1.z, pa1.w};
#pragma unroll
            for (int j = 0; j < 8; j++) An[(sa_k + j) * 132 + sa_m] = tf32split(av[j]);
            float bv[4] = {pb.x, pb.y, pb.z, pb.w};
#pragma unroll
            for (int j = 0; j < 4; j++) Bn[(sb_k + j) * 68 + sb_n] = tf32split(bv[j]);
            __syncthreads();
        }
        p ^= 1;
    }

    // ---- epilogue ----
#pragma unroll
    for (int mf = 0; mf < 2; mf++) {
#pragma unroll
        for (int nf = 0; nf < 4; nf++) {
            const int r0 = m0 + warpM * 32 + mf * 16 + g;
            const int r1 = r0 + 8;
            float c0 = acc[mf][nf][0], c1 = acc[mf][nf][1];
            float c2 = acc[mf][nf][2], c3 = acc[mf][nf][3];
            if (MODE == 0) {
                const int h = blockIdx.x;
                const int i = warpN * 16 + nf * 4 + tg;
                float* dstbase = blockIdx.z ? g_kf : g_qf;
                if (blockIdx.z) {
                    const float b0 = g_bk2[h * 64 + 2 * i];
                    const float b1 = g_bk2[h * 64 + 2 * i + 1];
                    c0 += b0; c1 += b1; c2 += b0; c3 += b1;
                }
                {
                    const int t = r0 & 1023, bb = r0 >> 10;
                    float2 rc = g_ropetab[t * 32 + i];
                    float* qp = &dstbase[(((size_t)(bb * H_TOT + h)) * T_LEN + t) * DH];
                    qp[i]      = c0 * rc.x - c1 * rc.y;
                    qp[i + 32] = c0 * rc.y + c1 * rc.x;
                }
                {
                    const int t = r1 & 1023, bb = r1 >> 10;
                    float2 rc = g_ropetab[t * 32 + i];
                    float* qp = &dstbase[(((size_t)(bb * H_TOT + h)) * T_LEN + t) * DH];
                    qp[i]      = c2 * rc.x - c3 * rc.y;
                    qp[i + 32] = c2 * rc.y + c3 * rc.x;
                }
            } else {
                const int nc = n0 + warpN * 32 + nf * 8 + 2 * tg;
                float* base = g_part + (size_t)blockIdx.z * M_ROWS * D_MODEL;
                *(float2*)&base[(size_t)r0 * 768 + nc] = make_float2(c0, c1);
                *(float2*)&base[(size_t)r1 * 768 + nc] = make_float2(c2, c3);
            }
        }
    }
}

// ================= reduce =================
__global__ __launch_bounds__(256) void reduce_kernel(const float* __restrict__ WOb,
                                                     float* __restrict__ Y) {
    const size_t i4 = (size_t)blockIdx.x * 256 + threadIdx.x;
    const size_t base = i4 * 4;
    const int nc = (int)(base % 768);
    float4 p0 = *(const float4*)&g_part[base];
    float4 p1 = *(const float4*)&g_part[base + (size_t)M_ROWS * D_MODEL];
    float4 p2 = *(const float4*)&g_part[base + (size_t)2 * M_ROWS * D_MODEL];
    float4 p3 = *(const float4*)&g_part[base + (size_t)3 * M_ROWS * D_MODEL];
    float4 o;
    o.x = 0.25f * (p0.x + p1.x + p2.x + p3.x) + 0.25f * (WOb[nc]     + WOb[768 + nc]     + WOb[1536 + nc]     + WOb[2304 + nc]);
    o.y = 0.25f * (p0.y + p1.y + p2.y + p3.y) + 0.25f * (WOb[nc + 1] + WOb[768 + nc + 1] + WOb[1536 + nc + 1] + WOb[2304 + nc + 1]);
    o.z = 0.25f * (p0.z + p1.z + p2.z + p3.z) + 0.25f * (WOb[nc + 2] + WOb[768 + nc + 2] + WOb[1536 + nc + 2] + WOb[2304 + nc + 2]);
    o.w = 0.25f * (p0.w + p1.w + p2.w + p3.w) + 0.25f * (WOb[nc + 3] + WOb[768 + nc + 3] + WOb[1536 + nc + 3] + WOb[2304 + nc + 3]);
    *(float4*)&Y[base] = o;
}

// ---- online softmax + top-4 update ----
#define SMTK_UPDATE(sc, sidx, mrun, lrun, s0v, s1v, s2v, s3v, i0v, i1v, i2v, i3v) \
    do {                                                                          \
        if ((sc) <= (mrun)) { (lrun) += __expf((sc) - (mrun)); }                  \
        else { (lrun) = fmaf((lrun), __expf((mrun) - (sc)), 1.0f); (mrun) = (sc); } \
        if ((sc) > (s3v)) {                                                       \
            if ((sc) > (s2v)) {                                                   \
                (s3v) = (s2v); (i3v) = (i2v);                                     \
                if ((sc) > (s1v)) {                                               \
                    (s2v) = (s1v); (i2v) = (i1v);                                 \
                    if ((sc) > (s0v)) {                                           \
                        (s1v) = (s0v); (i1v) = (i0v);                             \
                        (s0v) = (sc); (i0v) = (sidx);                             \
                    } else { (s1v) = (sc); (i1v) = (sidx); }                      \
                } else { (s2v) = (sc); (i2v) = (sidx); }                          \
            } else { (s3v) = (sc); (i3v) = (sidx); }                              \
        }                                                                         \
    } while (0)

// merge insert with tie-break (score desc, index asc)
#define MERGE_INS(sc, ix)                                                         \
    do {                                                                          \
        if ((sc) > bs3 || ((sc) == bs3 && (ix) < bi3)) {                          \
            if ((sc) > bs2 || ((sc) == bs2 && (ix) < bi2)) {                      \
                bs3 = bs2; bi3 = bi2;                                             \
                if ((sc) > bs1 || ((sc) == bs1 && (ix) < bi1)) {                  \
                    bs2 = bs1; bi2 = bi1;                                         \
                    if ((sc) > bs0 || ((sc) == bs0 && (ix) < bi0)) {              \
                        bs1 = bs0; bi1 = bi0; bs0 = (sc); bi0 = (ix);             \
                    } else { bs1 = (sc); bi1 = (ix); }                            \
                } else { bs2 = (sc); bi2 = (ix); }                                \
            } else { bs3 = (sc); bi3 = (ix); }                                    \
        }                                                                         \
    } while (0)

// ================= attn1: 4-way s-phase split, 512 thr = 128 rows x 4 phases =====
// smem: 128x64 K tile (32 KB); reused at the end for the partial-merge buffer.
__global__ __launch_bounds__(512) void attn1_kernel(const float* __restrict__ sink) {
    extern __shared__ float ks[];            // 8192 floats
    const int bh = blockIdx.y, h = bh % H_TOT;
    const int xt = (gridDim.x - 1) - blockIdx.x;   // heavy tiles first
    const int t0 = xt * 128;
    const int tid = threadIdx.x;
    const int row = tid & 127;
    const int ph  = tid >> 7;                // 0..3
    const int tA = t0 + row;

    u64 q2[32];
    {
        const ulonglong2* qp = (const ulonglong2*)&g_qf[((size_t)bh * T_LEN + tA) * DH];
#pragma unroll
        for (int i = 0; i < 16; i++) { ulonglong2 v = qp[i]; q2[2 * i] = v.x; q2[2 * i + 1] = v.y; }
    }

    float mrun = -CUDART_INF_F, lrun = 0.f;
    float ts0 = -CUDART_INF_F, ts1 = -CUDART_INF_F, ts2 = -CUDART_INF_F, ts3 = -CUDART_INF_F;
    int ti0 = 0, ti1 = 0, ti2 = 0, ti3 = 0;

    for (int s0 = 0; s0 <= t0; s0 += 128) {
        __syncthreads();
        {
            const float4* kg = (const float4*)&g_kf[((size_t)bh * T_LEN + s0) * DH];
            float4* d4 = (float4*)ks;
#pragma unroll
            for (int j = 0; j < 4; j++) d4[tid + j * 512] = kg[tid + j * 512];
        }
        __syncthreads();

        const int sMax = min(tA, s0 + 127);
        for (int s = s0 + ph; s <= sMax; s += 4) {
            const u64* kr = (const u64*)(ks + (s - s0) * DH);
            u64 a0 = 0ull, a1 = 0ull, a2 = 0ull, a3 = 0ull;
#pragma unroll
            for (int i = 0; i < 32; i += 4) {
                a0 = f2fma(q2[i],     kr[i],     a0);
                a1 = f2fma(q2[i + 1], kr[i + 1], a1);
                a2 = f2fma(q2[i + 2], kr[i + 2], a2);
                a3 = f2fma(q2[i + 3], kr[i + 3], a3);
            }
            float sc = ((f2sum(a0) + f2sum(a1)) + (f2sum(a2) + f2sum(a3))) * 0.125f;
            SMTK_UPDATE(sc, s, mrun, lrun, ts0, ts1, ts2, ts3, ti0, ti1, ti2, ti3);
        }
    }

    // ---- merge 4 phases per row (reuse ks as scratch) ----
    __syncthreads();
    float* Pm = ks;              // 512
    float* Pl = ks + 512;        // 512
    float* Ps = ks + 1024;       // 512*4
    int*   Pi = (int*)(ks + 3072);   // 512*4
    Pm[tid] = mrun; Pl[tid] = lrun;
    Ps[tid * 4 + 0] = ts0; Ps[tid * 4 + 1] = ts1; Ps[tid * 4 + 2] = ts2; Ps[tid * 4 + 3] = ts3;
    Pi[tid * 4 + 0] = ti0; Pi[tid * 4 + 1] = ti1; Pi[tid * 4 + 2] = ti2; Pi[tid * 4 + 3] = ti3;
    __syncthreads();

    if (tid < 128) {
        float m0v = Pm[tid], m1v = Pm[tid + 128], m2v = Pm[tid + 256], m3v = Pm[tid + 384];
        float mm = fmaxf(fmaxf(m0v, m1v), fmaxf(m2v, m3v));
        float ll = Pl[tid]       * __expf(m0v - mm)
                 + Pl[tid + 128] * __expf(m1v - mm)
                 + Pl[tid + 256] * __expf(m2v - mm)
                 + Pl[tid + 384] * __expf(m3v - mm);

        float bs0 = -CUDART_INF_F, bs1 = -CUDART_INF_F, bs2 = -CUDART_INF_F, bs3 = -CUDART_INF_F;
        int bi0 = 0x7fffffff, bi1 = 0x7fffffff, bi2 = 0x7fffffff, bi3 = 0x7fffffff;
#pragma unroll
        for (int pp = 0; pp < 4; pp++) {
            const int pidx = pp * 128 + tid;
#pragma unroll
            for (int j = 0; j < 4; j++) {
                float sc = Ps[pidx * 4 + j];
                int   ix = Pi[pidx * 4 + j];
                MERGE_INS(sc, ix);
            }
        }
        // sanitize unused slots (scores -inf -> weight 0; clamp idx)
        if (bi0 == 0x7fffffff) bi0 = 0;
        if (bi1 == 0x7fffffff) bi1 = 0;
        if (bi2 == 0x7fffffff) bi2 = 0;
        if (bi3 == 0x7fffffff) bi3 = 0;

        const float skv = sink[h];
        const float mf = fmaxf(mm, skv);
        const float Z = ll * __expf(mm - mf) + __expf(skv - mf);
        const float invZ = 1.0f / Z;
        float p0 = __expf(bs0 - mf) * invZ;
        float p1 = __expf(bs1 - mf) * invZ;
        float p2 = __expf(bs2 - mf) * invZ;
        float p3 = __expf(bs3 - mf) * invZ;
        const float winv = 1.0f / (p0 + p1 + p2 + p3 + 1e-9f);
        const int o = bh * T_LEN + tA;
        g_topi[o]  = make_int4(bi0, bi1, bi2, bi3);
        g_topw[o]  = make_float4(p0 * winv, p1 * winv, p2 * winv, p3 * winv);
        g_psink[o] = __expf(skv - mf) * invZ;
    }
}

// ================= attn2 =================
__global__ __launch_bounds__(256) void attn2_kernel(const float* __restrict__ vnull,
                                                    const float* __restrict__ V1w,
                                                    const float* __restrict__ V1b,
                                                    const float* __restrict__ V2w,
                                                    const float* __restrict__ V2b) {
    extern __shared__ float sm2[];
    float* V1s = sm2;                 // 16384
    float* V2t = sm2 + 16384;         // 256*66
    __shared__ float sV1b[256];
    __shared__ float sV2b[64];

    const int bh = blockIdx.y, b = bh / H_TOT, h = bh % H_TOT;
    const int t = blockIdx.x * 256 + threadIdx.x;

    for (int i = threadIdx.x; i < 4096; i += 256) ((float4*)V1s)[i] = ((const float4*)V1w)[i];
    for (int i = threadIdx.x; i < 16384; i += 256) {
        int dd = i >> 8, j = i & 255;
        V2t[j * 66 + dd] = V2w[i];
    }
    if (threadIdx.x < 256) sV1b[threadIdx.x] = V1b[threadIdx.x];
    if (threadIdx.x < 64)  sV2b[threadIdx.x] = V2b[threadIdx.x];
    __syncthreads();

    const int o = bh * T_LEN + t;
    const int4 ti = g_topi[o];
    const float4 pw = g_topw[o];
    const float psink = g_psink[o];

    u64 mk[32];
    {
        const float4* kp0 = (const float4*)&g_kf[((size_t)bh * T_LEN + ti.x) * DH];
        const float4* kp1 = (const float4*)&g_kf[((size_t)bh * T_LEN + ti.y) * DH];
        const float4* kp2 = (const float4*)&g_kf[((size_t)bh * T_LEN + ti.z) * DH];
        const float4* kp3 = (const float4*)&g_kf[((size_t)bh * T_LEN + ti.w) * DH];
#pragma unroll
        for (int i = 0; i < 16; i++) {
            float4 a = kp0[i], c = kp1[i], e = kp2[i], f = kp3[i];
            float v0 = pw.x * a.x + pw.y * c.x + pw.z * e.x + pw.w * f.x;
            float v1 = pw.x * a.y + pw.y * c.y + pw.z * e.y + pw.w * f.y;
            float v2 = pw.x * a.z + pw.y * c.z + pw.z * e.z + pw.w * f.z;
            float v3 = pw.x * a.w + pw.y * c.w + pw.z * e.w + pw.w * f.w;
            mk[2 * i]     = f2pack(v0, v1);
            mk[2 * i + 1] = f2pack(v2, v3);
        }
    }

    u64 out2[32];
#pragma unroll
    for (int i = 0; i < 32; i++) out2[i] = *(const u64*)&sV2b[2 * i];

    for (int j = 0; j < 256; ++j) {
        const ulonglong2* v1 = (const ulonglong2*)(V1s + j * 64);
        u64 z0 = 0ull, z1 = 0ull, z2 = 0ull, z3 = 0ull;
#pragma unroll
        for (int i = 0; i < 16; i += 2) {
            ulonglong2 va = v1[i];
            ulonglong2 vb = v1[i + 1];
            z0 = f2fma(mk[2 * i],     va.x, z0);
            z1 = f2fma(mk[2 * i + 1], va.y, z1);
            z2 = f2fma(mk[2 * i + 2], vb.x, z2);
            z3 = f2fma(mk[2 * i + 3], vb.y, z3);
        }
        float z = ((f2sum(z0) + f2sum(z1)) + (f2sum(z2) + f2sum(z3))) + sV1b[j];
        float gl = 0.5f * z * (1.0f + erff(z * 0.70710678118f));
        u64 g2 = f2pack(gl, gl);
        const u64* v2 = (const u64*)(V2t + j * 66);
#pragma unroll
        for (int i = 0; i < 32; i++) out2[i] = f2fma(g2, v2[i], out2[i]);
    }

    const int br = h / 12, hj = h % 12;
    float* outp = &g_ctx[((size_t)(b * T_LEN + t)) * NQ + br * D_MODEL + hj * 64];
    const float* vn = vnull + h * 64;
#pragma unroll
    for (int i = 0; i < 32; i++) {
        float2 v = f2unpack(out2[i]);
        v.x = fmaf(psink, vn[2 * i], v.x);
        v.y = fmaf(psink, vn[2 * i + 1], v.y);
        ((float2*)outp)[i] = v;
    }
}

// ================= launcher =================
extern "C" void kernel_launch(void* const* d_in, const int* in_sizes, int n_in,
                              void* d_out, int out_size) {
    const float* A      = (const float*)d_in[0];
    const float* X      = (const float*)d_in[1];
    const float* WKw    = (const float*)d_in[2];
    const float* WKb    = (const float*)d_in[3];
    const float* WQw    = (const float*)d_in[4];
    const float* wedgeA = (const float*)d_in[5];
    const float* wbias  = (const float*)d_in[6];
    const float* sink   = (const float*)d_in[7];
    const float* vnull  = (const float*)d_in[8];
    const float* V1w    = (const float*)d_in[9];
    const float* V1b    = (const float*)d_in[10];
    const float* V2w    = (const float*)d_in[11];
    const float* V2b    = (const float*)d_in[12];
    const float* WOw    = (const float*)d_in[13];
    const float* WOb    = (const float*)d_in[14];
    float* Y = (float*)d_out;

    cudaFuncSetAttribute(gemm_tf32_kernel<0>, cudaFuncAttributeMaxDynamicSharedMemorySize, 51200);
    cudaFuncSetAttribute(gemm_tf32_kernel<2>, cudaFuncAttributeMaxDynamicSharedMemorySize, 51200);
    cudaFuncSetAttribute(attn1_kernel, cudaFuncAttributeMaxDynamicSharedMemorySize, 32768);
    cudaFuncSetAttribute(attn2_kernel, cudaFuncAttributeMaxDynamicSharedMemorySize, 133120);

    // 1) weights prep
    prep_w<<<3456, 256>>>(WQw, WKw, WKb, wedgeA, wbias, WOw);
    // 2) rope table
    ropetab_kernel<<<128, 256>>>();
    // 3) Q+K projections + rope
    gemm_tf32_kernel<0><<<dim3(48, 16, 2), 256, 51200>>>(A, X, 768);
    // 4) attention scores / softmax / top-4  (<- ncu capture slot)
    attn1_kernel<<<dim3(8, 96), 512, 32768>>>(sink);
    // 5) marker + MLP + sink
    attn2_kernel<<<dim3(4, 96), 256, 133120>>>(vnull, V1w, V1b, V2w, V2b);
    // 6) output projection, split-K over branches
    gemm_tf32_kernel<2><<<dim3(12, 16, 4), 256, 51200>>>(nullptr, nullptr, 768);
    // 7) combine partials + bias
    reduce_kernel<<<1536, 256>>>(WOb, Y);
}

// round 11
// speedup vs baseline: 1.4304x; 1.0028x over previous
#include <cuda_runtime.h>
#include <math.h>
#include <math_constants.h>

#define D_MODEL 768
#define N_BR    4
#define DH      64
#define H_TOT   48
#define BATCH   2
#define T_LEN   1024
#define M_ROWS  2048
#define NQ      3072

typedef unsigned long long u64;
typedef unsigned int u32;

// ---- packed fp32x2 helpers ----
__device__ __forceinline__ u64 f2fma(u64 a, u64 b, u64 c) {
    u64 d; asm("fma.rn.f32x2 %0, %1, %2, %3;" : "=l"(d) : "l"(a), "l"(b), "l"(c)); return d;
}
__device__ __forceinline__ u64 f2add(u64 a, u64 b) {
    u64 d; asm("add.rn.f32x2 %0, %1, %2;" : "=l"(d) : "l"(a), "l"(b)); return d;
}
__device__ __forceinline__ u64 f2pack(float lo, float hi) {
    u64 d; asm("mov.b64 %0, {%1, %2};" : "=l"(d) : "f"(lo), "f"(hi)); return d;
}
__device__ __forceinline__ float2 f2unpack(u64 a) {
    float lo, hi; asm("mov.b64 {%0, %1}, %2;" : "=f"(lo), "=f"(hi) : "l"(a)); return make_float2(lo, hi);
}
__device__ __forceinline__ float f2sum(u64 a) { float2 v = f2unpack(a); return v.x + v.y; }

// ---- tf32 split ----
__device__ __forceinline__ float2 tf32split(float x) {
    u32 hb; asm("cvt.rna.tf32.f32 %0, %1;" : "=r"(hb) : "f"(x));
    float hf = __uint_as_float(hb);
    float lo = x - hf;
    u32 lb; asm("cvt.rna.tf32.f32 %0, %1;" : "=r"(lb) : "f"(lo));
    return make_float2(hf, __uint_as_float(lb));
}

#define MMA_TF32(ACC, A0, A1, A2, A3, B0, B1)                                        \
    asm volatile("mma.sync.aligned.m16n8k8.row.col.f32.tf32.tf32.f32 "               \
                 "{%0,%1,%2,%3}, {%4,%5,%6,%7}, {%8,%9}, {%0,%1,%2,%3};"             \
                 : "+f"(ACC[0]), "+f"(ACC[1]), "+f"(ACC[2]), "+f"(ACC[3])            \
                 : "r"(A0), "r"(A1), "r"(A2), "r"(A3), "r"(B0), "r"(B1))

// ---- scratch ----
__device__ float  g_wq2f[NQ * D_MODEL];
__device__ float  g_wk2f[NQ * D_MODEL];
__device__ float  g_bk2 [NQ];
__device__ float  g_wotf[D_MODEL * NQ];
__device__ float  g_qf  [(size_t)M_ROWS * NQ];
__device__ float  g_kf  [(size_t)M_ROWS * NQ];
__device__ float  g_ctx [(size_t)M_ROWS * NQ];
__device__ float  g_part[(size_t)N_BR * M_ROWS * D_MODEL];
__device__ float2 g_ropetab[T_LEN * 32];
__device__ int4   g_topi [BATCH * H_TOT * T_LEN];
__device__ float4 g_topw [BATCH * H_TOT * T_LEN];
__device__ float  g_psink[BATCH * H_TOT * T_LEN];

// ================= prep_w =================
__global__ __launch_bounds__(256) void prep_w(const float* __restrict__ WQw,
                                              const float* __restrict__ WKw,
                                              const float* __restrict__ WKb,
                                              const float* __restrict__ wedgeA,
                                              const float* __restrict__ wbias,
                                              const float* __restrict__ WOw) {
    __shared__ float sk[4096];
    __shared__ float Ws[64 * 68];
    __shared__ float tile[32][33];
    const int blk = blockIdx.x, tid = threadIdx.x;

    if (blk < 1152) {
        const bool isK = blk >= 576;
        const int b2 = isK ? blk - 576 : blk;
        const int h = b2 / 12, c0 = (b2 % 12) * 64;
        const int hs = isK ? (h % 12) : h;
        const float* Wsrc = isK ? WKw : WQw;
        for (int i = tid; i < 4096; i += 256) {
            int e = i >> 6, d = i & 63;
            sk[i] = wedgeA[e * 64 + d] - wedgeA[d * 64 + e];
        }
        for (int i = tid; i < 4096; i += 256) {
            int e = i >> 6, c = i & 63;
            Ws[e * 68 + c] = Wsrc[(size_t)(hs * 64 + e) * D_MODEL + c0 + c];
        }
        __syncthreads();
        const int d = tid >> 2, cg = (tid & 3) * 16;
        float outv[16];
        const float bd = 1.0f + wbias[h * 64 + d];
#pragma unroll
        for (int u = 0; u < 16; u++) outv[u] = bd * Ws[d * 68 + cg + u];
        for (int e = 0; e < 64; ++e) {
            float s = sk[e * 64 + d];
            const float* wr = &Ws[e * 68 + cg];
#pragma unroll
            for (int u = 0; u < 16; u++) outv[u] = fmaf(s, wr[u], outv[u]);
        }
        float* dst = (isK ? g_wk2f : g_wq2f) + (size_t)(h * 64 + d) * D_MODEL + c0 + cg;
#pragma unroll
        for (int u = 0; u < 16; u++) dst[u] = outv[u];

        if (isK && c0 == 0 && tid < 64) {
            float acc = (1.0f + wbias[h * 64 + tid]) * WKb[hs * 64 + tid];
            for (int s = 0; s < 64; ++s) acc += sk[s * 64 + tid] * WKb[hs * 64 + s];
            g_bk2[h * 64 + tid] = acc;
        }
    } else {
        const int b3 = blk - 1152;
        const int br = b3 / 576, rem = b3 % 576;
        const int cb = (rem / 24) * 32, nb = (rem % 24) * 32;
        const int tx = tid & 31, ty = tid >> 5;
        for (int r = ty; r < 32; r += 8)
            tile[r][tx] = WOw[((size_t)br * D_MODEL + cb + r) * D_MODEL + nb + tx];
        __syncthreads();
        for (int r = ty; r < 32; r += 8)
            g_wotf[(size_t)(nb + r) * NQ + br * D_MODEL + cb + tx] = tile[tx][r];
    }
}

// ================= rope table =================
__global__ void ropetab_kernel() {
    int idx = blockIdx.x * 256 + threadIdx.x;
    int t = idx >> 5, i = idx & 31;
    float inv = exp2f(-(float)i * 0.41524101186092034f);
    float fr = (float)t * inv;
    g_ropetab[idx] = make_float2(cosf(fr), sinf(fr));
}

// ================= tf32-3x NT GEMM, double-buffered, in-loop split ===============
template <int MODE>
__global__ __launch_bounds__(256) void gemm_tf32_kernel(const float* __restrict__ A0,
                                                        const float* __restrict__ A1,
                                                        int K) {
    extern __shared__ float2 smg[];
    float2* Abuf = smg;            // 2 x 16*132
    float2* Bbuf = smg + 4224;     // 2 x 16*68

    const int tid = threadIdx.x;
    const int m0 = blockIdx.y * 128, n0 = blockIdx.x * 64;
    const int warpId = tid >> 5, lane = tid & 31;
    const int warpM = warpId & 3, warpN = warpId >> 2;
    const int g = lane >> 2, tg = lane & 3;
    const int sa_m = tid >> 1, sa_k = (tid & 1) * 8;
    const int sb_n = tid & 63, sb_k = (tid >> 6) * 4;

    const float* Aop;
    const float* Bop;
    int ldA, ldB;
    if (MODE == 0) {
        Aop = blockIdx.z ? A1 : A0;
        Bop = blockIdx.z ? g_wk2f : g_wq2f;
        ldA = 768; ldB = 768;
    } else {
        Aop = g_ctx  + blockIdx.z * 768;
        Bop = g_wotf + blockIdx.z * 768;
        ldA = 3072; ldB = 3072;
    }

    float acc[2][4][4];
#pragma unroll
    for (int mf = 0; mf < 2; mf++)
#pragma unroll
        for (int nf = 0; nf < 4; nf++)
#pragma unroll
            for (int r = 0; r < 4; r++) acc[mf][nf][r] = 0.f;

    const float* Arow = Aop + (size_t)(m0 + sa_m) * ldA + sa_k;
    const float* Brow = Bop + (size_t)(n0 + sb_n) * ldB + sb_k;

    float4 pa0 = *(const float4*)(Arow);
    float4 pa1 = *(const float4*)(Arow + 4);
    float4 pb  = *(const float4*)(Brow);

    {
        float av[8] = {pa0.x, pa0.y, pa0.z, pa0.w, pa1.x, pa1.y, pa1.z, pa1.w};
#pragma unroll
        for (int j = 0; j < 8; j++) Abuf[(sa_k + j) * 132 + sa_m] = tf32split(av[j]);
        float bv[4] = {pb.x, pb.y, pb.z, pb.w};
#pragma unroll
        for (int j = 0; j < 4; j++) Bbuf[(sb_k + j) * 68 + sb_n] = tf32split(bv[j]);
    }
    __syncthreads();

    int p = 0;
    for (int k0 = 0; k0 < K; k0 += 16) {
        const bool more = (k0 + 16) < K;
        if (more) {
            pa0 = *(const float4*)(Arow + k0 + 16);
            pa1 = *(const float4*)(Arow + k0 + 20);
            pb  = *(const float4*)(Brow + k0 + 16);
        }
        const float2* As2 = Abuf + p * 2112;
        const float2* Bs2 = Bbuf + p * 1088;
#pragma unroll
        for (int ks = 0; ks < 16; ks += 8) {
            float2 fa[2][4];
#pragma unroll
            for (int mf = 0; mf < 2; mf++) {
                const int rI = warpM * 32 + mf * 16 + g;
                const float2* c0p = &As2[(ks + tg) * 132];
                const float2* c4p = &As2[(ks + tg + 4) * 132];
                fa[mf][0] = c0p[rI];
                fa[mf][1] = c0p[rI + 8];
                fa[mf][2] = c4p[rI];
                fa[mf][3] = c4p[rI + 8];
            }
            float2 fb[4][2];
#pragma unroll
            for (int nf = 0; nf < 4; nf++) {
                const int cI = warpN * 32 + nf * 8 + g;
                fb[nf][0] = Bs2[(ks + tg) * 68 + cI];
                fb[nf][1] = Bs2[(ks + tg + 4) * 68 + cI];
            }
#pragma unroll
            for (int mf = 0; mf < 2; mf++) {
                const u32 ah0 = __float_as_uint(fa[mf][0].x), al0 = __float_as_uint(fa[mf][0].y);
                const u32 ah1 = __float_as_uint(fa[mf][1].x), al1 = __float_as_uint(fa[mf][1].y);
                const u32 ah2 = __float_as_uint(fa[mf][2].x), al2 = __float_as_uint(fa[mf][2].y);
                const u32 ah3 = __float_as_uint(fa[mf][3].x), al3 = __float_as_uint(fa[mf][3].y);
#pragma unroll
                for (int nf = 0; nf < 4; nf++) {
                    const u32 bh0 = __float_as_uint(fb[nf][0].x), bl0 = __float_as_uint(fb[nf][0].y);
                    const u32 bh1 = __float_as_uint(fb[nf][1].x), bl1 = __float_as_uint(fb[nf][1].y);
                    MMA_TF32(acc[mf][nf], al0, al1, al2, al3, bh0, bh1);
                    MMA_TF32(acc[mf][nf], ah0, ah1, ah2, ah3, bl0, bl1);
                    MMA_TF32(acc[mf][nf], ah0, ah1, ah2, ah3, bh0, bh1);
                }
            }
        }
        if (more) {
            float2* An = Abuf + (p ^ 1) * 2112;
            float2* Bn = Bbuf + (p ^ 1) * 1088;
            float av[8] = {pa0.x, pa0.y, pa0.z, pa0.w, pa1.x, pa1.y, pa1.z, pa1.w};
#pragma unroll
            for (int j = 0; j < 8; j++) An[(sa_k + j) * 132 + sa_m] = tf32split(av[j]);
            float bv[4] = {pb.x, pb.y, pb.z, pb.w};
#pragma unroll
            for (int j = 0; j < 4; j++) Bn[(sb_k + j) * 68 + sb_n] = tf32split(bv[j]);
            __syncthreads();
        }
        p ^= 1;
    }

    // ---- epilogue ----
#pragma unroll
    for (int mf = 0; mf < 2; mf++) {
#pragma unroll
        for (int nf = 0; nf < 4; nf++) {
            const int r0 = m0 + warpM * 32 + mf * 16 + g;
            const int r1 = r0 + 8;
            float c0 = acc[mf][nf][0], c1 = acc[mf][nf][1];
            float c2 = acc[mf][nf][2], c3 = acc[mf][nf][3];
            if (MODE == 0) {
                const int h = blockIdx.x;
                const int i = warpN * 16 + nf * 4 + tg;
                float* dstbase = blockIdx.z ? g_kf : g_qf;
                if (blockIdx.z) {
                    const float b0 = g_bk2[h * 64 + 2 * i];
                    const float b1 = g_bk2[h * 64 + 2 * i + 1];
                    c0 += b0; c1 += b1; c2 += b0; c3 += b1;
                }
                {
                    const int t = r0 & 1023, bb = r0 >> 10;
                    float2 rc = g_ropetab[t * 32 + i];
                    float* qp = &dstbase[(((size_t)(bb * H_TOT + h)) * T_LEN + t) * DH];
                    qp[i]      = c0 * rc.x - c1 * rc.y;
                    qp[i + 32] = c0 * rc.y + c1 * rc.x;
                }
                {
                    const int t = r1 & 1023, bb = r1 >> 10;
                    float2 rc = g_ropetab[t * 32 + i];
                    float* qp = &dstbase[(((size_t)(bb * H_TOT + h)) * T_LEN + t) * DH];
                    qp[i]      = c2 * rc.x - c3 * rc.y;
                    qp[i + 32] = c2 * rc.y + c3 * rc.x;
                }
            } else {
                const int nc = n0 + warpN * 32 + nf * 8 + 2 * tg;
                float* base = g_part + (size_t)blockIdx.z * M_ROWS * D_MODEL;
                *(float2*)&base[(size_t)r0 * 768 + nc] = make_float2(c0, c1);
                *(float2*)&base[(size_t)r1 * 768 + nc] = make_float2(c2, c3);
            }
        }
    }
}

// ================= reduce =================
__global__ __launch_bounds__(256) void reduce_kernel(const float* __restrict__ WOb,
                                                     float* __restrict__ Y) {
    const size_t i4 = (size_t)blockIdx.x * 256 + threadIdx.x;
    const size_t base = i4 * 4;
    const int nc = (int)(base % 768);
    float4 p0 = *(const float4*)&g_part[base];
    float4 p1 = *(const float4*)&g_part[base + (size_t)M_ROWS * D_MODEL];
    float4 p2 = *(const float4*)&g_part[base + (size_t)2 * M_ROWS * D_MODEL];
    float4 p3 = *(const float4*)&g_part[base + (size_t)3 * M_ROWS * D_MODEL];
    float4 o;
    o.x = 0.25f * (p0.x + p1.x + p2.x + p3.x) + 0.25f * (WOb[nc]     + WOb[768 + nc]     + WOb[1536 + nc]     + WOb[2304 + nc]);
    o.y = 0.25f * (p0.y + p1.y + p2.y + p3.y) + 0.25f * (WOb[nc + 1] + WOb[768 + nc + 1] + WOb[1536 + nc + 1] + WOb[2304 + nc + 1]);
    o.z = 0.25f * (p0.z + p1.z + p2.z + p3.z) + 0.25f * (WOb[nc + 2] + WOb[768 + nc + 2] + WOb[1536 + nc + 2] + WOb[2304 + nc + 2]);
    o.w = 0.25f * (p0.w + p1.w + p2.w + p3.w) + 0.25f * (WOb[nc + 3] + WOb[768 + nc + 3] + WOb[1536 + nc + 3] + WOb[2304 + nc + 3]);
    *(float4*)&Y[base] = o;
}

// ---- online softmax + top-4 update ----
#define SMTK_UPDATE(sc, sidx, mrun, lrun, s0v, s1v, s2v, s3v, i0v, i1v, i2v, i3v) \
    do {                                                                          \
        if ((sc) <= (mrun)) { (lrun) += __expf((sc) - (mrun)); }                  \
        else { (lrun) = fmaf((lrun), __expf((mrun) - (sc)), 1.0f); (mrun) = (sc); } \
        if ((sc) > (s3v)) {                                                       \
            if ((sc) > (s2v)) {                                                   \
                (s3v) = (s2v); (i3v) = (i2v);                                     \
                if ((sc) > (s1v)) {                                               \
                    (s2v) = (s1v); (i2v) = (i1v);                                 \
                    if ((sc) > (s0v)) {                                           \
                        (s1v) = (s0v); (i1v) = (i0v);                             \
                        (s0v) = (sc); (i0v) = (sidx);                             \
                    } else { (s1v) = (sc); (i1v) = (sidx); }                      \
                } else { (s2v) = (sc); (i2v) = (sidx); }                          \
            } else { (s3v) = (sc); (i3v) = (sidx); }                              \
        }                                                                         \
    } while (0)

#define MERGE_INS(sc, ix)                                                         \
    do {                                                                          \
        if ((sc) > bs3 || ((sc) == bs3 && (ix) < bi3)) {                          \
            if ((sc) > bs2 || ((sc) == bs2 && (ix) < bi2)) {                      \
                bs3 = bs2; bi3 = bi2;                                             \
                if ((sc) > bs1 || ((sc) == bs1 && (ix) < bi1)) {                  \
                    bs2 = bs1; bi2 = bi1;                                         \
                    if ((sc) > bs0 || ((sc) == bs0 && (ix) < bi0)) {              \
                        bs1 = bs0; bi1 = bi0; bs0 = (sc); bi0 = (ix);             \
                    } else { bs1 = (sc); bi1 = (ix); }                            \
                } else { bs2 = (sc); bi2 = (ix); }                                \
            } else { bs3 = (sc); bi3 = (ix); }                                    \
        }                                                                         \
    } while (0)

// ================= attn1: 4-way s-phase split, LDS.128 k reads ===================
__global__ __launch_bounds__(512) void attn1_kernel(const float* __restrict__ sink) {
    extern __shared__ float ks[];            // 8192 floats
    const int bh = blockIdx.y, h = bh % H_TOT;
    const int xt = (gridDim.x - 1) - blockIdx.x;
    const int t0 = xt * 128;
    const int tid = threadIdx.x;
    const int row = tid & 127;
    const int ph  = tid >> 7;                // 0..3
    const int tA = t0 + row;

    u64 q2[32];
    {
        const ulonglong2* qp = (const ulonglong2*)&g_qf[((size_t)bh * T_LEN + tA) * DH];
#pragma unroll
        for (int i = 0; i < 16; i++) { ulonglong2 v = qp[i]; q2[2 * i] = v.x; q2[2 * i + 1] = v.y; }
    }

    float mrun = -CUDART_INF_F, lrun = 0.f;
    float ts0 = -CUDART_INF_F, ts1 = -CUDART_INF_F, ts2 = -CUDART_INF_F, ts3 = -CUDART_INF_F;
    int ti0 = 0, ti1 = 0, ti2 = 0, ti3 = 0;

    for (int s0 = 0; s0 <= t0; s0 += 128) {
        __syncthreads();
        {
            const float4* kg = (const float4*)&g_kf[((size_t)bh * T_LEN + s0) * DH];
            float4* d4 = (float4*)ks;
#pragma unroll
            for (int j = 0; j < 4; j++) d4[tid + j * 512] = kg[tid + j * 512];
        }
        __syncthreads();

        const int sMax = min(tA, s0 + 127);
        for (int s = s0 + ph; s <= sMax; s += 4) {
            const ulonglong2* kr = (const ulonglong2*)(ks + (s - s0) * DH);
            u64 a0 = 0ull, a1 = 0ull, a2 = 0ull, a3 = 0ull;
#pragma unroll
            for (int i = 0; i < 16; i += 4) {
                ulonglong2 k01 = kr[i];
                ulonglong2 k23 = kr[i + 1];
                ulonglong2 k45 = kr[i + 2];
                ulonglong2 k67 = kr[i + 3];
                a0 = f2fma(q2[2 * i],     k01.x, a0);
                a1 = f2fma(q2[2 * i + 1], k01.y, a1);
                a2 = f2fma(q2[2 * i + 2], k23.x, a2);
                a3 = f2fma(q2[2 * i + 3], k23.y, a3);
                a0 = f2fma(q2[2 * i + 4], k45.x, a0);
                a1 = f2fma(q2[2 * i + 5], k45.y, a1);
                a2 = f2fma(q2[2 * i + 6], k67.x, a2);
                a3 = f2fma(q2[2 * i + 7], k67.y, a3);
            }
            u64 s01 = f2add(a0, a1);
            u64 s23 = f2add(a2, a3);
            float2 sv = f2unpack(f2add(s01, s23));
            float sc = (sv.x + sv.y) * 0.125f;
            SMTK_UPDATE(sc, s, mrun, lrun, ts0, ts1, ts2, ts3, ti0, ti1, ti2, ti3);
        }
    }

    // ---- merge 4 phases per row (reuse ks as scratch) ----
    __syncthreads();
    float* Pm = ks;
    float* Pl = ks + 512;
    float* Ps = ks + 1024;
    int*   Pi = (int*)(ks + 3072);
    Pm[tid] = mrun; Pl[tid] = lrun;
    Ps[tid * 4 + 0] = ts0; Ps[tid * 4 + 1] = ts1; Ps[tid * 4 + 2] = ts2; Ps[tid * 4 + 3] = ts3;
    Pi[tid * 4 + 0] = ti0; Pi[tid * 4 + 1] = ti1; Pi[tid * 4 + 2] = ti2; Pi[tid * 4 + 3] = ti3;
    __syncthreads();

    if (tid < 128) {
        float m0v = Pm[tid], m1v = Pm[tid + 128], m2v = Pm[tid + 256], m3v = Pm[tid + 384];
        float mm = fmaxf(fmaxf(m0v, m1v), fmaxf(m2v, m3v));
        float ll = Pl[tid]       * __expf(m0v - mm)
                 + Pl[tid + 128] * __expf(m1v - mm)
                 + Pl[tid + 256] * __expf(m2v - mm)
                 + Pl[tid + 384] * __expf(m3v - mm);

        float bs0 = -CUDART_INF_F, bs1 = -CUDART_INF_F, bs2 = -CUDART_INF_F, bs3 = -CUDART_INF_F;
        int bi0 = 0x7fffffff, bi1 = 0x7fffffff, bi2 = 0x7fffffff, bi3 = 0x7fffffff;
#pragma unroll
        for (int pp = 0; pp < 4; pp++) {
            const int pidx = pp * 128 + tid;
#pragma unroll
            for (int j = 0; j < 4; j++) {
                float sc = Ps[pidx * 4 + j];
                int   ix = Pi[pidx * 4 + j];
                MERGE_INS(sc, ix);
            }
        }
        if (bi0 == 0x7fffffff) bi0 = 0;
        if (bi1 == 0x7fffffff) bi1 = 0;
        if (bi2 == 0x7fffffff) bi2 = 0;
        if (bi3 == 0x7fffffff) bi3 = 0;

        const float skv = sink[h];
        const float mf = fmaxf(mm, skv);
        const float Z = ll * __expf(mm - mf) + __expf(skv - mf);
        const float invZ = 1.0f / Z;
        float p0 = __expf(bs0 - mf) * invZ;
        float p1 = __expf(bs1 - mf) * invZ;
        float p2 = __expf(bs2 - mf) * invZ;
        float p3 = __expf(bs3 - mf) * invZ;
        const float winv = 1.0f / (p0 + p1 + p2 + p3 + 1e-9f);
        const int o = bh * T_LEN + tA;
        g_topi[o]  = make_int4(bi0, bi1, bi2, bi3);
        g_topw[o]  = make_float4(p0 * winv, p1 * winv, p2 * winv, p3 * winv);
        g_psink[o] = __expf(skv - mf) * invZ;
    }
}

// ================= attn2 =================
__global__ __launch_bounds__(256) void attn2_kernel(const float* __restrict__ vnull,
                                                    const float* __restrict__ V1w,
                                                    const float* __restrict__ V1b,
                                                    const float* __restrict__ V2w,
                                                    const float* __restrict__ V2b) {
    extern __shared__ float sm2[];
    float* V1s = sm2;
    float* V2t = sm2 + 16384;
    __shared__ float sV1b[256];
    __shared__ float sV2b[64];

    const int bh = blockIdx.y, b = bh / H_TOT, h = bh % H_TOT;
    const int t = blockIdx.x * 256 + threadIdx.x;

    for (int i = threadIdx.x; i < 4096; i += 256) ((float4*)V1s)[i] = ((const float4*)V1w)[i];
    for (int i = threadIdx.x; i < 16384; i += 256) {
        int dd = i >> 8, j = i & 255;
        V2t[j * 66 + dd] = V2w[i];
    }
    if (threadIdx.x < 256) sV1b[threadIdx.x] = V1b[threadIdx.x];
    if (threadIdx.x < 64)  sV2b[threadIdx.x] = V2b[threadIdx.x];
    __syncthreads();

    const int o = bh * T_LEN + t;
    const int4 ti = g_topi[o];
    const float4 pw = g_topw[o];
    const float psink = g_psink[o];

    u64 mk[32];
    {
        const float4* kp0 = (const float4*)&g_kf[((size_t)bh * T_LEN + ti.x) * DH];
        const float4* kp1 = (const float4*)&g_kf[((size_t)bh * T_LEN + ti.y) * DH];
        const float4* kp2 = (const float4*)&g_kf[((size_t)bh * T_LEN + ti.z) * DH];
        const float4* kp3 = (const float4*)&g_kf[((size_t)bh * T_LEN + ti.w) * DH];
#pragma unroll
        for (int i = 0; i < 16; i++) {
            float4 a = kp0[i], c = kp1[i], e = kp2[i], f = kp3[i];
            float v0 = pw.x * a.x + pw.y * c.x + pw.z * e.x + pw.w * f.x;
            float v1 = pw.x * a.y + pw.y * c.y + pw.z * e.y + pw.w * f.y;
            float v2 = pw.x * a.z + pw.y * c.z + pw.z * e.z + pw.w * f.z;
            float v3 = pw.x * a.w + pw.y * c.w + pw.z * e.w + pw.w * f.w;
            mk[2 * i]     = f2pack(v0, v1);
            mk[2 * i + 1] = f2pack(v2, v3);
        }
    }

    u64 out2[32];
#pragma unroll
    for (int i = 0; i < 32; i++) out2[i] = *(const u64*)&sV2b[2 * i];

    for (int j = 0; j < 256; ++j) {
        const ulonglong2* v1 = (const ulonglong2*)(V1s + j * 64);
        u64 z0 = 0ull, z1 = 0ull, z2 = 0ull, z3 = 0ull;
#pragma unroll
        for (int i = 0; i < 16; i += 2) {
            ulonglong2 va = v1[i];
            ulonglong2 vb = v1[i + 1];
            z0 = f2fma(mk[2 * i],     va.x, z0);
            z1 = f2fma(mk[2 * i + 1], va.y, z1);
            z2 = f2fma(mk[2 * i + 2], vb.x, z2);
            z3 = f2fma(mk[2 * i + 3], vb.y, z3);
        }
        float z = ((f2sum(z0) + f2sum(z1)) + (f2sum(z2) + f2sum(z3))) + sV1b[j];
        float gl = 0.5f * z * (1.0f + erff(z * 0.70710678118f));
        u64 g2 = f2pack(gl, gl);
        const u64* v2 = (const u64*)(V2t + j * 66);
#pragma unroll
        for (int i = 0; i < 32; i++) out2[i] = f2fma(g2, v2[i], out2[i]);
    }

    const int br = h / 12, hj = h % 12;
    float* outp = &g_ctx[((size_t)(b * T_LEN + t)) * NQ + br * D_MODEL + hj * 64];
    const float* vn = vnull + h * 64;
#pragma unroll
    for (int i = 0; i < 32; i++) {
        float2 v = f2unpack(out2[i]);
        v.x = fmaf(psink, vn[2 * i], v.x);
        v.y = fmaf(psink, vn[2 * i + 1], v.y);
        ((float2*)outp)[i] = v;
    }
}

// ================= launcher =================
extern "C" void kernel_launch(void* const* d_in, const int* in_sizes, int n_in,
                              void* d_out, int out_size) {
    const float* A      = (const float*)d_in[0];
    const float* X      = (const float*)d_in[1];
    const float* WKw    = (const float*)d_in[2];
    const float* WKb    = (const float*)d_in[3];
    const float* WQw    = (const float*)d_in[4];
    const float* wedgeA = (const float*)d_in[5];
    const float* wbias  = (const float*)d_in[6];
    const float* sink   = (const float*)d_in[7];
    const float* vnull  = (const float*)d_in[8];
    const float* V1w    = (const float*)d_in[9];
    const float* V1b    = (const float*)d_in[10];
    const float* V2w    = (const float*)d_in[11];
    const float* V2b    = (const float*)d_in[12];
    const float* WOw    = (const float*)d_in[13];
    const float* WOb    = (const float*)d_in[14];
    float* Y = (float*)d_out;

    cudaFuncSetAttribute(gemm_tf32_kernel<0>, cudaFuncAttributeMaxDynamicSharedMemorySize, 51200);
    cudaFuncSetAttribute(gemm_tf32_kernel<2>, cudaFuncAttributeMaxDynamicSharedMemorySize, 51200);
    cudaFuncSetAttribute(attn1_kernel, cudaFuncAttributeMaxDynamicSharedMemorySize, 32768);
    cudaFuncSetAttribute(attn2_kernel, cudaFuncAttributeMaxDynamicSharedMemorySize, 133120);

    prep_w<<<3456, 256>>>(WQw, WKw, WKb, wedgeA, wbias, WOw);
    ropetab_kernel<<<128, 256>>>();
    gemm_tf32_kernel<0><<<dim3(48, 16, 2), 256, 51200>>>(A, X, 768);
    attn1_kernel<<<dim3(8, 96), 512, 32768>>>(sink);
    attn2_kernel<<<dim3(4, 96), 256, 133120>>>(vnull, V1w, V1b, V2w, V2b);
    gemm_tf32_kernel<2><<<dim3(12, 16, 4), 256, 51200>>>(nullptr, nullptr, 768);
    reduce_kernel<<<1536, 256>>>(WOb, Y);
}